// round 11
// baseline (speedup 1.0000x reference)
#include <cuda_runtime.h>
#include <math.h>
#include <stdint.h>

#define D 128
#define MAXN 50048           // 391 * 128, multiple of 128
#define EMAX 409600
#define TPB 256

// ---------------- scratch (static device globals; no allocations) ----------------
__device__ __align__(16) float g_emb[4][(size_t)MAXN * D];
__device__ __align__(16) float g_h  [4][(size_t)MAXN * D];
__device__ __align__(16) float g_agg[4][(size_t)MAXN * D];
__device__ __align__(16) float g_qkv[4][(size_t)MAXN * 384];
__device__ int   g_cnt   [4][MAXN];
__device__ int   g_rowptr[4][MAXN + 1];
__device__ int   g_wofs  [4][MAXN];
__device__ int   g_psum  [4][64];
__device__ int   g_total [4];
__device__ int   g_csr_src[4][EMAX];
__device__ float g_csr_c [4][EMAX];
__device__ __align__(16) float g_dinv[4][MAXN];
__device__ __align__(16) float g_rels[4][D];
__device__ double g_sum[4][D];
__device__ double g_sumsq[4][D];
__device__ __align__(16) float g_scale[4][D];
__device__ __align__(16) float g_shift[4][D];
__device__ double g_scores[4];

// ---------------- helpers ----------------
__device__ __forceinline__ uint32_t f2tf(float x) {
    uint32_t u;
    asm("cvt.rna.tf32.f32 %0, %1;" : "=r"(u) : "f"(x));
    return u;
}
__device__ __forceinline__ void mma_tf32(float* c, const uint32_t* a, const uint32_t* b) {
    asm volatile(
        "mma.sync.aligned.m16n8k8.row.col.f32.tf32.tf32.f32 "
        "{%0,%1,%2,%3}, {%4,%5,%6,%7}, {%8,%9}, {%0,%1,%2,%3};"
        : "+f"(c[0]), "+f"(c[1]), "+f"(c[2]), "+f"(c[3])
        : "r"(a[0]), "r"(a[1]), "r"(a[2]), "r"(a[3]), "r"(b[0]), "r"(b[1]));
}
__device__ __forceinline__ void cp16(uint32_t dst, const void* src) {
    asm volatile("cp.async.cg.shared.global [%0], [%1], 16;" :: "r"(dst), "l"(src));
}
__device__ __forceinline__ long sel4(int z, long4 v) {
    return (z == 0) ? v.x : (z == 1) ? v.y : (z == 2) ? v.z : v.w;
}

// ---------------- init: emb[0] = features; permute rels; zero counters/stats/scores ----
__global__ void k_init(const float* __restrict__ feat, const float* __restrict__ rel_emb, int Nn) {
    size_t idx = (size_t)blockIdx.x * blockDim.x + threadIdx.x;
    size_t tot = (size_t)Nn * D;
    if (idx < tot) {
        g_emb[0][idx] = feat[idx];
    }
    if (idx < 4 * (size_t)MAXN) ((int*)g_cnt)[idx] = 0;
    if (idx < 4 * D) {
        const int perm[4] = {3, 0, 1, 2};
        int r = (int)(idx / D), j = (int)(idx % D);
        g_rels[r][j] = rel_emb[perm[r] * D + j];
        ((double*)g_sum)[idx] = 0.0;
        ((double*)g_sumsq)[idx] = 0.0;
    }
    if (idx < 4) g_scores[idx] = 0.0;
}

// zero scratch tail rows [Nn, MAXN) so GEMM A-cp.async loads need no bounds checks
__global__ void k_zero_tail(int Nn) {
    size_t tail = (size_t)(MAXN - Nn) * D;
    size_t idx = (size_t)blockIdx.x * blockDim.x + threadIdx.x;
    if (idx >= tail) return;
    size_t o = (size_t)Nn * D + idx;
    #pragma unroll
    for (int r = 0; r < 4; r++) { g_emb[r][o] = 0.f; g_h[r][o] = 0.f; g_agg[r][o] = 0.f; }
}

// ---------------- CSR build ----------------
__global__ void k_hist(const int* __restrict__ edge, int E) {
    const int perm[4] = {3, 0, 1, 2};
    int r = blockIdx.y;
    const int* dst = edge + ((size_t)perm[r] * 2 + 1) * E;
    int t = blockIdx.x * blockDim.x + threadIdx.x;
    if (t < E) atomicAdd(&g_cnt[r][dst[t]], 1);
}

__global__ void k_scan1(int Nn) {     // grid (nb, 4) x 1024; also computes dinv
    int r = blockIdx.y, t = threadIdx.x;
    int i = blockIdx.x * 1024 + t;
    int v = (i < Nn) ? g_cnt[r][i] : 0;
    if (i < Nn) g_dinv[r][i] = rsqrtf((float)v + 1.0f);
    int x = v;
    #pragma unroll
    for (int o = 1; o < 32; o <<= 1) {
        int y = __shfl_up_sync(0xFFFFFFFFu, x, o);
        if ((t & 31) >= o) x += y;
    }
    __shared__ int ws[32];
    if ((t & 31) == 31) ws[t >> 5] = x;
    __syncthreads();
    if (t < 32) {
        int y = ws[t];
        #pragma unroll
        for (int o = 1; o < 32; o <<= 1) {
            int z = __shfl_up_sync(0xFFFFFFFFu, y, o);
            if (t >= o) y += z;
        }
        ws[t] = y;
    }
    __syncthreads();
    int off = (t >= 32) ? ws[(t >> 5) - 1] : 0;
    int incl = x + off;
    if (i < Nn) g_rowptr[r][i] = incl - v;
    if (t == 1023) g_psum[r][blockIdx.x] = incl;
}

__global__ void k_scan2(int nb) {     // grid 4 x 64
    int r = blockIdx.x, t = threadIdx.x;
    int v = (t < nb) ? g_psum[r][t] : 0;
    int x = v;
    #pragma unroll
    for (int o = 1; o < 32; o <<= 1) {
        int y = __shfl_up_sync(0xFFFFFFFFu, x, o);
        if ((t & 31) >= o) x += y;
    }
    __shared__ int w2[2];
    if ((t & 31) == 31) w2[t >> 5] = x;
    __syncthreads();
    int off = (t >= 32) ? w2[0] : 0;
    int incl = x + off;
    g_psum[r][t] = incl - v;
    if (t == 63) g_total[r] = incl;
}

__global__ void k_scan3(int Nn) {     // grid (nb, 4) x 1024
    int r = blockIdx.y;
    int i = blockIdx.x * 1024 + threadIdx.x;
    if (i < Nn) {
        int val = g_rowptr[r][i] + g_psum[r][blockIdx.x];
        g_rowptr[r][i] = val;
        g_wofs[r][i] = val;
    }
    if (i == 0) g_rowptr[r][Nn] = g_total[r];
}

__global__ void k_fill(const int* __restrict__ edge, int E) {
    const int perm[4] = {3, 0, 1, 2};
    int r = blockIdx.y;
    const int* src = edge + ((size_t)perm[r] * 2) * E;
    const int* dst = src + E;
    int e = blockIdx.x * blockDim.x + threadIdx.x;
    if (e >= E) return;
    int s = src[e], d = dst[e];
    int pos = atomicAdd(&g_wofs[r][d], 1);
    g_csr_src[r][pos] = s;
    g_csr_c[r][pos] = g_dinv[r][s] * g_dinv[r][d];
}

// ---------------- batched pipelined TF32 GEMM ----------------
// BM=128 BN=128 BK=32, 256 threads, cp.async 2-stage double buffer (B always; A when !APPLY).
// z = blockIdx.z selects batch slice via long4 offsets.
// EPI:   0 plain store (+bias), 1 blend (C = (acc+bias)*alpha[z] + (1-alpha)*stk),
//        2 score (no store; sum lrelu(acc+bias)*q -> scores[z]).
// APPLY: 0 none; 1/2: A[m,k] = base[m,k] + lrelu(A_in[m,k]*bn_scale[z,k]+bn_shift[z,k]);
//        2 additionally stores the computed A to ap_store (+ a_off[z]).
template <bool TRANSB, bool SCALE_A, bool BIAS, int EPI, int APPLY>
__global__ void __launch_bounds__(256) k_gemm_tf32(
    const float* __restrict__ A_base, long4 a_off,
    const float* __restrict__ Bm,
    float* __restrict__ C_base, long4 c_off,
    int M, int N, int K,
    const float* __restrict__ cs_base,
    const float* __restrict__ bias,
    const float* __restrict__ ep_base, long4 ep_off,
    const float* __restrict__ alphas,
    double* __restrict__ scores,
    const float* __restrict__ ap_base, long4 ap_off,
    const float* __restrict__ bn_scale, const float* __restrict__ bn_shift,
    float* __restrict__ ap_store)
{
    extern __shared__ uint32_t sm[];
    __shared__ float s_cs[128];
    const int tid = threadIdx.x;
    const int lane = tid & 31, wid = tid >> 5;
    const int z = blockIdx.z;
    const long ao = sel4(z, a_off);
    const long co = sel4(z, c_off);
    const long eo = sel4(z, ep_off);
    const float* A = A_base + ao;
    float* C = C_base + co;
    const float* APB = (APPLY != 0) ? (ap_base + sel4(z, ap_off)) : nullptr;
    float* ST = (APPLY == 2) ? (ap_store + ao) : nullptr;
    const int bm = blockIdx.y * 128;
    const int bn = blockIdx.x * 128;
    const int warp_m = (wid & 3) * 32;
    const int warp_n = (wid >> 2) * 64;
    const uint32_t smem_u = (uint32_t)__cvta_generic_to_shared(sm);
    float* smf = (float*)sm;

    if (SCALE_A && tid < 128) s_cs[tid] = cs_base[z * 128 + tid];

    float acc[2][8][4];
    #pragma unroll
    for (int i = 0; i < 2; i++)
        #pragma unroll
        for (int j = 0; j < 8; j++)
            #pragma unroll
            for (int q = 0; q < 4; q++) acc[i][j][q] = 0.0f;

    auto load_stage = [&](int st, int k0) {
        if (APPLY == 0) {
            #pragma unroll
            for (int i = 0; i < 4; i++) {
                int id = tid + i * 256;
                int m = id >> 3, c = id & 7;
                cp16(smem_u + (uint32_t)(st * 4608 + m * 36 + c * 4) * 4,
                     A + (size_t)(bm + m) * K + k0 + c * 4);
            }
        } else {
            int ka = tid & 31;
            int gk = k0 + ka;
            float scl = bn_scale[z * 128 + gk];
            float shf = bn_shift[z * 128 + gk];
            int m0 = tid >> 5;
            #pragma unroll
            for (int i = 0; i < 16; i++) {
                int m = m0 + i * 8;
                int row = bm + m;
                float v = 0.0f;
                if (row < M) {
                    float a = A[(size_t)row * K + gk];
                    float t = a * scl + shf;
                    t = t > 0.0f ? t : 0.01f * t;
                    v = t + APB[(size_t)row * K + gk];
                    if (APPLY == 2) ST[(size_t)row * K + gk] = v;
                }
                smf[st * 4608 + m * 36 + ka] = v;
            }
        }
        if (TRANSB) {
            #pragma unroll
            for (int i = 0; i < 4; i++) {
                int id = tid + i * 256;
                int n = id >> 3, c = id & 7;
                cp16(smem_u + (uint32_t)(9216 + st * 4608 + n * 36 + c * 4) * 4,
                     Bm + (size_t)(bn + n) * K + k0 + c * 4);
            }
        } else {
            #pragma unroll
            for (int i = 0; i < 4; i++) {
                int id = tid + i * 256;
                int k = id >> 5, c = id & 31;
                cp16(smem_u + (uint32_t)(9216 + st * 4352 + k * 136 + c * 4) * 4,
                     Bm + (size_t)(k0 + k) * N + bn + c * 4);
            }
        }
    };

    const int r0 = lane >> 2, c0 = lane & 3;
    const int nk = K >> 5;

    load_stage(0, 0);
    asm volatile("cp.async.commit_group;");

    for (int kt = 0; kt < nk; kt++) {
        const int cur = kt & 1;
        const int k0g = kt << 5;
        if (kt + 1 < nk) {
            load_stage((kt + 1) & 1, (kt + 1) << 5);
            asm volatile("cp.async.commit_group;");
            asm volatile("cp.async.wait_group 1;");
        } else {
            asm volatile("cp.async.wait_group 0;");
        }
        __syncthreads();

        #pragma unroll
        for (int ks = 0; ks < 32; ks += 8) {
            uint32_t a[2][4], b[8][2];
            float cs0 = 1.0f, cs1 = 1.0f;
            if (SCALE_A) { cs0 = s_cs[k0g + ks + c0]; cs1 = s_cs[k0g + ks + 4 + c0]; }
            #pragma unroll
            for (int fm = 0; fm < 2; fm++) {
                int mb = warp_m + fm * 16;
                const uint32_t* Ab = sm + cur * 4608;
                float v0 = __uint_as_float(Ab[(mb + r0) * 36 + ks + c0]);
                float v1 = __uint_as_float(Ab[(mb + 8 + r0) * 36 + ks + c0]);
                float v2 = __uint_as_float(Ab[(mb + r0) * 36 + ks + 4 + c0]);
                float v3 = __uint_as_float(Ab[(mb + 8 + r0) * 36 + ks + 4 + c0]);
                if (SCALE_A) { v0 *= cs0; v1 *= cs0; v2 *= cs1; v3 *= cs1; }
                a[fm][0] = f2tf(v0); a[fm][1] = f2tf(v1);
                a[fm][2] = f2tf(v2); a[fm][3] = f2tf(v3);
            }
            if (TRANSB) {
                const uint32_t* Bb = sm + 9216 + cur * 4608;
                #pragma unroll
                for (int fn = 0; fn < 8; fn++) {
                    int nb = warp_n + fn * 8 + r0;
                    b[fn][0] = f2tf(__uint_as_float(Bb[nb * 36 + ks + c0]));
                    b[fn][1] = f2tf(__uint_as_float(Bb[nb * 36 + ks + 4 + c0]));
                }
            } else {
                const uint32_t* Bb = sm + 9216 + cur * 4352;
                #pragma unroll
                for (int fn = 0; fn < 8; fn++) {
                    int nb = warp_n + fn * 8 + r0;
                    b[fn][0] = f2tf(__uint_as_float(Bb[(ks + c0) * 136 + nb]));
                    b[fn][1] = f2tf(__uint_as_float(Bb[(ks + 4 + c0) * 136 + nb]));
                }
            }
            #pragma unroll
            for (int fm = 0; fm < 2; fm++)
                #pragma unroll
                for (int fn = 0; fn < 8; fn++)
                    mma_tf32(acc[fm][fn], a[fm], b[fn]);
        }
        __syncthreads();
    }

    // ---- epilogue ----
    const int cc = (lane & 3) * 2;
    float alpha = 0.f, oma = 0.f;
    if (EPI == 1) { alpha = alphas[z]; oma = 1.0f - alpha; }
    const float* EP = (EPI != 0) ? (ep_base + (EPI == 1 ? eo : 0)) : nullptr;
    float score_local = 0.0f;

    #pragma unroll
    for (int fm = 0; fm < 2; fm++) {
        #pragma unroll
        for (int fn = 0; fn < 8; fn++) {
            int row = bm + warp_m + fm * 16 + r0;
            int col = bn + warp_n + fn * 8 + cc;
            float b0 = BIAS ? bias[col] : 0.0f;
            float b1 = BIAS ? bias[col + 1] : 0.0f;
            float v00 = acc[fm][fn][0] + b0, v01 = acc[fm][fn][1] + b1;
            float v10 = acc[fm][fn][2] + b0, v11 = acc[fm][fn][3] + b1;
            if (EPI == 0) {
                if (row < M)     *(float2*)(C + (size_t)row * N + col)       = make_float2(v00, v01);
                if (row + 8 < M) *(float2*)(C + (size_t)(row + 8) * N + col) = make_float2(v10, v11);
            } else if (EPI == 1) {
                if (row < M) {
                    float2 s = *(const float2*)(EP + (size_t)row * N + col);
                    *(float2*)(C + (size_t)row * N + col) =
                        make_float2(v00 * alpha + oma * s.x, v01 * alpha + oma * s.y);
                }
                if (row + 8 < M) {
                    float2 s = *(const float2*)(EP + (size_t)(row + 8) * N + col);
                    *(float2*)(C + (size_t)(row + 8) * N + col) =
                        make_float2(v10 * alpha + oma * s.x, v11 * alpha + oma * s.y);
                }
            } else {
                float q0 = EP[col], q1 = EP[col + 1];
                if (row < M) {
                    float l0 = v00 > 0.f ? v00 : 0.01f * v00;
                    float l1 = v01 > 0.f ? v01 : 0.01f * v01;
                    score_local += l0 * q0 + l1 * q1;
                }
                if (row + 8 < M) {
                    float l0 = v10 > 0.f ? v10 : 0.01f * v10;
                    float l1 = v11 > 0.f ? v11 : 0.01f * v11;
                    score_local += l0 * q0 + l1 * q1;
                }
            }
        }
    }

    if (EPI == 2) {
        __shared__ float sred[8];
        #pragma unroll
        for (int o = 16; o > 0; o >>= 1)
            score_local += __shfl_xor_sync(0xFFFFFFFFu, score_local, o);
        if (lane == 0) sred[wid] = score_local;
        __syncthreads();
        if (tid == 0) {
            float tot = 0.f;
            #pragma unroll
            for (int w = 0; w < 8; w++) tot += sred[w];
            atomicAdd(&scores[z], (double)tot);
        }
    }
}

// ---------------- CSR aggregation: persistent warps, 4-way unroll, fused BN stats ----
template <bool STATS>
__global__ void k_agg(const float* __restrict__ bias, int Nn) {
    int r = blockIdx.y;
    int lane = threadIdx.x & 31;
    int warp0 = blockIdx.x * (blockDim.x >> 5) + (threadIdx.x >> 5);
    int nwarps = gridDim.x * (blockDim.x >> 5);
    const float* h = g_h[r];
    const int* csr_src = g_csr_src[r];
    const float* csr_c = g_csr_c[r];
    float4 bv = ((const float4*)bias)[lane];

    double s0 = 0, s1 = 0, s2 = 0, s3 = 0;
    double q0 = 0, q1 = 0, q2 = 0, q3 = 0;

    for (int d = warp0; d < Nn; d += nwarps) {
        float di = g_dinv[r][d];
        float d2 = di * di;
        float4 acc = ((const float4*)(h + (size_t)d * D))[lane];
        acc.x = acc.x * d2 + bv.x;
        acc.y = acc.y * d2 + bv.y;
        acc.z = acc.z * d2 + bv.z;
        acc.w = acc.w * d2 + bv.w;
        int beg = g_rowptr[r][d], end = g_rowptr[r][d + 1];
        int e = beg;
        int end4 = beg + ((end - beg) & ~3);
        for (; e < end4; e += 4) {
            int sA = csr_src[e], sB = csr_src[e + 1], sC = csr_src[e + 2], sD = csr_src[e + 3];
            float cA = csr_c[e], cB = csr_c[e + 1], cC = csr_c[e + 2], cD = csr_c[e + 3];
            float4 hA = ((const float4*)(h + (size_t)sA * D))[lane];
            float4 hB = ((const float4*)(h + (size_t)sB * D))[lane];
            float4 hC = ((const float4*)(h + (size_t)sC * D))[lane];
            float4 hD = ((const float4*)(h + (size_t)sD * D))[lane];
            acc.x += hA.x * cA + hB.x * cB + hC.x * cC + hD.x * cD;
            acc.y += hA.y * cA + hB.y * cB + hC.y * cC + hD.y * cD;
            acc.z += hA.z * cA + hB.z * cB + hC.z * cC + hD.z * cD;
            acc.w += hA.w * cA + hB.w * cB + hC.w * cC + hD.w * cD;
        }
        for (; e < end; e++) {
            int s = csr_src[e];
            float c = csr_c[e];
            float4 hv = ((const float4*)(h + (size_t)s * D))[lane];
            acc.x += hv.x * c;
            acc.y += hv.y * c;
            acc.z += hv.z * c;
            acc.w += hv.w * c;
        }
        ((float4*)(g_agg[r] + (size_t)d * D))[lane] = acc;
        if (STATS) {
            s0 += acc.x; q0 += (double)acc.x * acc.x;
            s1 += acc.y; q1 += (double)acc.y * acc.y;
            s2 += acc.z; q2 += (double)acc.z * acc.z;
            s3 += acc.w; q3 += (double)acc.w * acc.w;
        }
    }

    if (STATS) {
        __shared__ double ssum[128], ssq[128];
        for (int t = threadIdx.x; t < 128; t += blockDim.x) { ssum[t] = 0.0; ssq[t] = 0.0; }
        __syncthreads();
        int c4 = lane * 4;
        atomicAdd(&ssum[c4 + 0], s0); atomicAdd(&ssq[c4 + 0], q0);
        atomicAdd(&ssum[c4 + 1], s1); atomicAdd(&ssq[c4 + 1], q1);
        atomicAdd(&ssum[c4 + 2], s2); atomicAdd(&ssq[c4 + 2], q2);
        atomicAdd(&ssum[c4 + 3], s3); atomicAdd(&ssq[c4 + 3], q3);
        __syncthreads();
        for (int t = threadIdx.x; t < 128; t += blockDim.x) {
            atomicAdd(&g_sum[r][t], ssum[t]);
            atomicAdd(&g_sumsq[r][t], ssq[t]);
        }
    }
}

// ---------------- BatchNorm finalize (re-zeros stats for the next layer) ----------------
__global__ void k_bn_final(const float* __restrict__ gamma, const float* __restrict__ beta, int Nn) {
    int t = threadIdx.x;   // 512
    int r = t >> 7, j = t & 127;
    double mean = g_sum[r][j] / Nn;
    double var = g_sumsq[r][j] / Nn - mean * mean;
    float sc = gamma[j] * (float)(1.0 / sqrt(var + 1e-5));
    g_scale[r][j] = sc;
    g_shift[r][j] = beta[j] - (float)mean * sc;
    g_sum[r][j] = 0.0;
    g_sumsq[r][j] = 0.0;
}

// ---------------- rels update ----------------
__global__ void k_rels_update(const float* __restrict__ Wrt, const float* __restrict__ brt) {
    __shared__ float cur[4 * D];
    int t = threadIdx.x;  // 512
    cur[t] = ((float*)g_rels)[t];
    __syncthreads();
    int r = t >> 7, j = t & 127;
    float s = brt[j];
    #pragma unroll 8
    for (int k = 0; k < D; k++) s = fmaf(cur[r * D + k], Wrt[j * D + k], s);
    ((float*)g_rels)[t] = s;
}

// ---------------- attention ----------------
__global__ void k_attn(int Nn) {
    int gw = (blockIdx.x * blockDim.x + threadIdx.x) >> 5;
    int lane = threadIdx.x & 31;
    if (gw >= Nn * 4) return;
    int n = gw >> 2, h = gw & 3;
    float q[4], kk[4], v[4];
    #pragma unroll
    for (int l = 0; l < 4; l++) {
        const float* base = g_qkv[l] + (size_t)n * 384 + h * 32 + lane;
        q[l]  = base[0] * 0.17677669529663687f;
        kk[l] = base[128];
        v[l]  = base[256];
    }
    float sc[4][4];
    #pragma unroll
    for (int l = 0; l < 4; l++)
        #pragma unroll
        for (int m = 0; m < 4; m++) {
            float p = q[l] * kk[m];
            p += __shfl_xor_sync(0xFFFFFFFFu, p, 16);
            p += __shfl_xor_sync(0xFFFFFFFFu, p, 8);
            p += __shfl_xor_sync(0xFFFFFFFFu, p, 4);
            p += __shfl_xor_sync(0xFFFFFFFFu, p, 2);
            p += __shfl_xor_sync(0xFFFFFFFFu, p, 1);
            sc[l][m] = p;
        }
    #pragma unroll
    for (int l = 0; l < 4; l++) {
        float mx = fmaxf(fmaxf(sc[l][0], sc[l][1]), fmaxf(sc[l][2], sc[l][3]));
        float e0 = expf(sc[l][0] - mx), e1 = expf(sc[l][1] - mx);
        float e2 = expf(sc[l][2] - mx), e3 = expf(sc[l][3] - mx);
        float inv = 1.0f / (e0 + e1 + e2 + e3);
        float o = (e0 * v[0] + e1 * v[1] + e2 * v[2] + e3 * v[3]) * inv;
        g_h[l][(size_t)n * D + h * 32 + lane] = o;
    }
}

// ---------------- final outputs (float4; coef computed inline per block) ----------------
__global__ void k_final(float* __restrict__ out, int Nn) {
    __shared__ float sco[4];
    if (threadIdx.x == 0) {
        double sv[4] = { g_scores[0] / Nn, g_scores[1] / Nn, g_scores[3] / Nn, g_scores[2] / Nn };
        double mx = sv[0];
        for (int i = 1; i < 4; i++) mx = sv[i] > mx ? sv[i] : mx;
        double e[4], ss = 0.0;
        for (int i = 0; i < 4; i++) { e[i] = exp(sv[i] - mx); ss += e[i]; }
        double w[4];
        for (int i = 0; i < 4; i++) w[i] = e[i] / ss;
        sco[0] = (float)w[0];
        sco[1] = (float)w[1];
        sco[2] = (float)w[3];
        sco[3] = (float)w[2];
    }
    __syncthreads();
    size_t i4 = (size_t)blockIdx.x * blockDim.x + threadIdx.x;
    size_t ND4 = (size_t)Nn * 32;
    if (i4 >= ND4) return;
    int c4 = (int)(i4 & 31) * 4;
    float4 e0 = ((const float4*)g_emb[0])[i4];
    float4 e1 = ((const float4*)g_emb[1])[i4];
    float4 e2 = ((const float4*)g_emb[2])[i4];
    float4 e3 = ((const float4*)g_emb[3])[i4];
    float w0 = sco[0], w1 = sco[1], w2 = sco[2], w3 = sco[3];
    float4 r4;
    r4.x = w0 * e0.x + w1 * e1.x + w2 * e2.x + w3 * e3.x;
    r4.y = w0 * e0.y + w1 * e1.y + w2 * e2.y + w3 * e3.y;
    r4.z = w0 * e0.z + w1 * e1.z + w2 * e2.z + w3 * e3.z;
    r4.w = w0 * e0.w + w1 * e1.w + w2 * e2.w + w3 * e3.w;
    float4* o4 = (float4*)out;
    o4[i4] = r4;
    float4 c;
    c = *(const float4*)(g_rels[3] + c4);
    o4[ND4 + i4]     = make_float4(r4.x * c.x, r4.y * c.y, r4.z * c.z, r4.w * c.w);
    c = *(const float4*)(g_rels[0] + c4);
    o4[2 * ND4 + i4] = make_float4(r4.x * c.x, r4.y * c.y, r4.z * c.z, r4.w * c.w);
    c = *(const float4*)(g_rels[1] + c4);
    o4[3 * ND4 + i4] = make_float4(r4.x * c.x, r4.y * c.y, r4.z * c.z, r4.w * c.w);
    c = *(const float4*)(g_rels[2] + c4);
    o4[4 * ND4 + i4] = make_float4(r4.x * c.x, r4.y * c.y, r4.z * c.z, r4.w * c.w);
}

// ---------------- host orchestration ----------------
extern "C" void kernel_launch(void* const* d_in, const int* in_sizes, int n_in,
                              void* d_out, int out_size) {
    const float* features   = (const float*)d_in[0];
    const float* rel_emb    = (const float*)d_in[1];
    const int*   edge_index = (const int*)  d_in[2];
    const float* W_gcn      = (const float*)d_in[3];
    const float* b_gcn      = (const float*)d_in[4];
    const float* bn_gamma   = (const float*)d_in[5];
    const float* bn_beta    = (const float*)d_in[6];
    const float* W_rt       = (const float*)d_in[7];
    const float* b_rt       = (const float*)d_in[8];
    const float* attn_w_in  = (const float*)d_in[9];
    const float* attn_b_in  = (const float*)d_in[10];
    const float* attn_w_out = (const float*)d_in[11];
    const float* attn_b_out = (const float*)d_in[12];
    const float* alphas     = (const float*)d_in[13];
    const float* fusion_q   = (const float*)d_in[14];
    const float* fusion_w   = (const float*)d_in[15];
    const float* fusion_b   = (const float*)d_in[16];

    int Nn = in_sizes[0] / D;
    int E  = in_sizes[2] / 8;
    if (Nn > MAXN || E > EMAX) return;

    static float *emb = nullptr, *h, *agg, *qkv, *rels, *scalep, *shiftp;
    static double *scores;
    static bool attr_done = false;
    if (!emb) {
        cudaGetSymbolAddress((void**)&emb,    g_emb);
        cudaGetSymbolAddress((void**)&h,      g_h);
        cudaGetSymbolAddress((void**)&agg,    g_agg);
        cudaGetSymbolAddress((void**)&qkv,    g_qkv);
        cudaGetSymbolAddress((void**)&rels,   g_rels);
        cudaGetSymbolAddress((void**)&scalep, g_scale);
        cudaGetSymbolAddress((void**)&shiftp, g_shift);
        cudaGetSymbolAddress((void**)&scores, g_scores);
    }
    const int SMEM_T  = 73728;
    const int SMEM_NT = 71680;
    if (!attr_done) {
        cudaFuncSetAttribute((const void*)k_gemm_tf32<false, true,  false, 0, 0>,
                             cudaFuncAttributeMaxDynamicSharedMemorySize, SMEM_NT);
        cudaFuncSetAttribute((const void*)k_gemm_tf32<false, true,  false, 0, 1>,
                             cudaFuncAttributeMaxDynamicSharedMemorySize, SMEM_NT);
        cudaFuncSetAttribute((const void*)k_gemm_tf32<false, true,  false, 0, 2>,
                             cudaFuncAttributeMaxDynamicSharedMemorySize, SMEM_NT);
        cudaFuncSetAttribute((const void*)k_gemm_tf32<true,  false, true,  0, 0>,
                             cudaFuncAttributeMaxDynamicSharedMemorySize, SMEM_T);
        cudaFuncSetAttribute((const void*)k_gemm_tf32<true,  false, true,  1, 0>,
                             cudaFuncAttributeMaxDynamicSharedMemorySize, SMEM_T);
        cudaFuncSetAttribute((const void*)k_gemm_tf32<true,  false, true,  2, 0>,
                             cudaFuncAttributeMaxDynamicSharedMemorySize, SMEM_T);
        attr_done = true;
    }

    const long S = (long)MAXN * D;
    const long Q = (long)MAXN * 384;
    const long4 ident = make_long4(0, S, 2 * S, 3 * S);
    const long4 smapo = make_long4(3 * S, 0, 2 * S, 1 * S);
    const long4 qoff  = make_long4(0, Q, 2 * Q, 3 * Q);
    const long4 zero4 = make_long4(0, 0, 0, 0);

    size_t ND = (size_t)Nn * D;
    int gElem = (int)((ND + TPB - 1) / TPB);
    int g4    = (int)(((size_t)Nn * 32 + TPB - 1) / TPB);
    int gEdge = (E + TPB - 1) / TPB;
    int gy    = (Nn + 127) / 128;
    int nb    = (Nn + 1023) / 1024;
    int gTail = (int)(((size_t)(MAXN - Nn) * D + TPB - 1) / TPB);

    k_init<<<gElem, TPB>>>(features, rel_emb, Nn);
    if (gTail > 0) k_zero_tail<<<gTail, TPB>>>(Nn);
    k_hist<<<dim3(gEdge, 4), TPB>>>(edge_index, E);
    k_scan1<<<dim3(nb, 4), 1024>>>(Nn);
    k_scan2<<<4, 64>>>(nb);
    k_scan3<<<dim3(nb, 4), 1024>>>(Nn);
    k_fill<<<dim3(gEdge, 4), TPB>>>(edge_index, E);

    // ---- layer 0: h[r] = (features * rels[r]) @ W0 ; emb[0] holds features ----
    k_gemm_tf32<false, true, false, 0, 0><<<dim3(1, gy, 4), 256, SMEM_NT>>>(
        emb, zero4, W_gcn, h, ident, Nn, D, D,
        rels, nullptr, nullptr, zero4, nullptr, nullptr,
        nullptr, zero4, nullptr, nullptr, nullptr);
    k_agg<true><<<dim3(624, 4), TPB>>>(b_gcn, Nn);
    k_bn_final<<<1, 512>>>(bn_gamma, bn_beta, Nn);
    k_rels_update<<<1, 512>>>(W_rt, b_rt);

    // ---- layer 1: A = emb_L0 = features + lrelu(bn0(agg0)) computed in-loader, stored ----
    k_gemm_tf32<false, true, false, 0, 2><<<dim3(1, gy, 4), 256, SMEM_NT>>>(
        agg, ident, W_gcn + (size_t)D * D, h, ident, Nn, D, D,
        rels, nullptr, nullptr, zero4, nullptr, nullptr,
        features, zero4, scalep, shiftp, emb);
    k_agg<true><<<dim3(624, 4), TPB>>>(b_gcn + D, Nn);
    k_bn_final<<<1, 512>>>(bn_gamma + D, bn_beta + D, Nn);
    k_rels_update<<<1, 512>>>(W_rt + (size_t)D * D, b_rt + D);

    // ---- layer 2: A = emb_L1 = emb_L0 + lrelu(bn1(agg1)) computed in-loader, NOT stored ----
    k_gemm_tf32<false, true, false, 0, 1><<<dim3(1, gy, 4), 256, SMEM_NT>>>(
        agg, ident, W_gcn + (size_t)2 * D * D, h, ident, Nn, D, D,
        rels, nullptr, nullptr, zero4, nullptr, nullptr,
        emb, ident, scalep, shiftp, nullptr);
    k_agg<false><<<dim3(624, 4), TPB>>>(b_gcn + 2 * D, Nn);
    k_rels_update<<<1, 512>>>(W_rt + (size_t)2 * D * D, b_rt + 2 * D);

    // QKV over stk[l] = agg[SMAP[l]]
    k_gemm_tf32<true, false, true, 0, 0><<<dim3(3, gy, 4), 256, SMEM_T>>>(
        agg, smapo, attn_w_in, qkv, qoff, Nn, 384, D,
        nullptr, attn_b_in, nullptr, zero4, nullptr, nullptr,
        nullptr, zero4, nullptr, nullptr, nullptr);
    k_attn<<<(int)(((size_t)Nn * 128 + TPB - 1) / TPB), TPB>>>(Nn);
    // out-proj + fused blend -> emb[l]
    k_gemm_tf32<true, false, true, 1, 0><<<dim3(1, gy, 4), 256, SMEM_T>>>(
        h, ident, attn_w_out, emb, ident, Nn, D, D,
        nullptr, attn_b_out, agg, smapo, alphas, nullptr,
        nullptr, zero4, nullptr, nullptr, nullptr);
    // fused score GEMMs
    k_gemm_tf32<true, false, true, 2, 0><<<dim3(1, gy, 4), 256, SMEM_T>>>(
        emb, ident, fusion_w, h, ident, Nn, D, D,
        nullptr, fusion_b, fusion_q, zero4, nullptr, scores,
        nullptr, zero4, nullptr, nullptr, nullptr);
    k_final<<<g4, TPB>>>((float*)d_out, Nn);
}

// round 12
// speedup vs baseline: 1.1812x; 1.1812x over previous
#include <cuda_runtime.h>
#include <math.h>
#include <stdint.h>

#define D 128
#define MAXN 50048           // 391 * 128, multiple of 128
#define EMAX 409600
#define TPB 256

// ---------------- scratch (static device globals; no allocations) ----------------
__device__ __align__(16) float g_emb[4][(size_t)MAXN * D];
__device__ __align__(16) float g_h  [4][(size_t)MAXN * D];
__device__ __align__(16) float g_agg[4][(size_t)MAXN * D];
__device__ __align__(16) float g_qkv[4][(size_t)MAXN * 384];
__device__ int   g_cnt   [4][MAXN];
__device__ int   g_rowptr[4][MAXN + 1];
__device__ int   g_wofs  [4][MAXN];
__device__ int   g_psum  [4][64];
__device__ int   g_total [4];
__device__ int   g_csr_src[4][EMAX];
__device__ float g_csr_c [4][EMAX];
__device__ __align__(16) float g_dinv[4][MAXN];
__device__ __align__(16) float g_rels[4][D];
__device__ double g_sum[4][D];
__device__ double g_sumsq[4][D];
__device__ __align__(16) float g_scale[4][D];
__device__ __align__(16) float g_shift[4][D];
__device__ double g_scores[4];

// ---------------- helpers ----------------
__device__ __forceinline__ uint32_t f2tf(float x) {
    uint32_t u;
    asm("cvt.rna.tf32.f32 %0, %1;" : "=r"(u) : "f"(x));
    return u;
}
__device__ __forceinline__ void mma_tf32(float* c, const uint32_t* a, const uint32_t* b) {
    asm volatile(
        "mma.sync.aligned.m16n8k8.row.col.f32.tf32.tf32.f32 "
        "{%0,%1,%2,%3}, {%4,%5,%6,%7}, {%8,%9}, {%0,%1,%2,%3};"
        : "+f"(c[0]), "+f"(c[1]), "+f"(c[2]), "+f"(c[3])
        : "r"(a[0]), "r"(a[1]), "r"(a[2]), "r"(a[3]), "r"(b[0]), "r"(b[1]));
}
__device__ __forceinline__ void cp16(uint32_t dst, const void* src) {
    asm volatile("cp.async.cg.shared.global [%0], [%1], 16;" :: "r"(dst), "l"(src));
}

// ---------------- init: emb[0] = features; permute rels; zero counters/stats/scores ----
__global__ void k_init(const float* __restrict__ feat, const float* __restrict__ rel_emb, int Nn) {
    size_t idx = (size_t)blockIdx.x * blockDim.x + threadIdx.x;
    size_t tot = (size_t)Nn * D;
    if (idx < tot) {
        g_emb[0][idx] = feat[idx];
    }
    if (idx < 4 * (size_t)MAXN) ((int*)g_cnt)[idx] = 0;
    if (idx < 4 * D) {
        const int perm[4] = {3, 0, 1, 2};
        int r = (int)(idx / D), j = (int)(idx % D);
        g_rels[r][j] = rel_emb[perm[r] * D + j];
        ((double*)g_sum)[idx] = 0.0;
        ((double*)g_sumsq)[idx] = 0.0;
    }
    if (idx < 4) g_scores[idx] = 0.0;
}

// zero scratch tail rows [Nn, MAXN) so GEMM A-cp.async loads need no bounds checks
__global__ void k_zero_tail(int Nn) {
    size_t tail = (size_t)(MAXN - Nn) * D;
    size_t idx = (size_t)blockIdx.x * blockDim.x + threadIdx.x;
    if (idx >= tail) return;
    size_t o = (size_t)Nn * D + idx;
    #pragma unroll
    for (int r = 0; r < 4; r++) { g_emb[r][o] = 0.f; g_h[r][o] = 0.f; g_agg[r][o] = 0.f; }
}

// ---------------- CSR build ----------------
__global__ void k_hist(const int* __restrict__ edge, int E) {
    const int perm[4] = {3, 0, 1, 2};
    int r = blockIdx.y;
    const int* dst = edge + ((size_t)perm[r] * 2 + 1) * E;
    int t = blockIdx.x * blockDim.x + threadIdx.x;
    if (t < E) atomicAdd(&g_cnt[r][dst[t]], 1);
}

__global__ void k_scan1(int Nn) {     // grid (nb, 4) x 1024; also computes dinv
    int r = blockIdx.y, t = threadIdx.x;
    int i = blockIdx.x * 1024 + t;
    int v = (i < Nn) ? g_cnt[r][i] : 0;
    if (i < Nn) g_dinv[r][i] = rsqrtf((float)v + 1.0f);
    int x = v;
    #pragma unroll
    for (int o = 1; o < 32; o <<= 1) {
        int y = __shfl_up_sync(0xFFFFFFFFu, x, o);
        if ((t & 31) >= o) x += y;
    }
    __shared__ int ws[32];
    if ((t & 31) == 31) ws[t >> 5] = x;
    __syncthreads();
    if (t < 32) {
        int y = ws[t];
        #pragma unroll
        for (int o = 1; o < 32; o <<= 1) {
            int z = __shfl_up_sync(0xFFFFFFFFu, y, o);
            if (t >= o) y += z;
        }
        ws[t] = y;
    }
    __syncthreads();
    int off = (t >= 32) ? ws[(t >> 5) - 1] : 0;
    int incl = x + off;
    if (i < Nn) g_rowptr[r][i] = incl - v;
    if (t == 1023) g_psum[r][blockIdx.x] = incl;
}

__global__ void k_scan2(int nb) {     // grid 4 x 64
    int r = blockIdx.x, t = threadIdx.x;
    int v = (t < nb) ? g_psum[r][t] : 0;
    int x = v;
    #pragma unroll
    for (int o = 1; o < 32; o <<= 1) {
        int y = __shfl_up_sync(0xFFFFFFFFu, x, o);
        if ((t & 31) >= o) x += y;
    }
    __shared__ int w2[2];
    if ((t & 31) == 31) w2[t >> 5] = x;
    __syncthreads();
    int off = (t >= 32) ? w2[0] : 0;
    int incl = x + off;
    g_psum[r][t] = incl - v;
    if (t == 63) g_total[r] = incl;
}

__global__ void k_scan3(int Nn) {     // grid (nb, 4) x 1024
    int r = blockIdx.y;
    int i = blockIdx.x * 1024 + threadIdx.x;
    if (i < Nn) {
        int val = g_rowptr[r][i] + g_psum[r][blockIdx.x];
        g_rowptr[r][i] = val;
        g_wofs[r][i] = val;
    }
    if (i == 0) g_rowptr[r][Nn] = g_total[r];
}

__global__ void k_fill(const int* __restrict__ edge, int E) {
    const int perm[4] = {3, 0, 1, 2};
    int r = blockIdx.y;
    const int* src = edge + ((size_t)perm[r] * 2) * E;
    const int* dst = src + E;
    int e = blockIdx.x * blockDim.x + threadIdx.x;
    if (e >= E) return;
    int s = src[e], d = dst[e];
    int pos = atomicAdd(&g_wofs[r][d], 1);
    g_csr_src[r][pos] = s;
    g_csr_c[r][pos] = g_dinv[r][s] * g_dinv[r][d];
}

// ---------------- batched pipelined TF32 GEMM ----------------
// BM=128 BN=128 BK=32, 256 threads, cp.async 2-stage double buffer.
// z = blockIdx.z selects batch slice via long4 offsets.
// EPI: 0 plain store (+bias), 1 blend (C = (acc+bias)*alpha[z] + (1-alpha)*stk),
//      2 score (no store; sum lrelu(acc+bias)*q -> scores[z]).
template <bool TRANSB, bool SCALE_A, bool BIAS, int EPI>
__global__ void __launch_bounds__(256) k_gemm_tf32(
    const float* __restrict__ A_base, long4 a_off,
    const float* __restrict__ Bm,
    float* __restrict__ C_base, long4 c_off,
    int M, int N, int K,
    const float* __restrict__ cs_base,
    const float* __restrict__ bias,
    const float* __restrict__ ep_base, long4 ep_off,
    const float* __restrict__ alphas,
    double* __restrict__ scores)
{
    extern __shared__ uint32_t sm[];
    __shared__ float s_cs[128];
    const int tid = threadIdx.x;
    const int lane = tid & 31, wid = tid >> 5;
    const int z = blockIdx.z;
    const long ao = (z == 0) ? a_off.x : (z == 1) ? a_off.y : (z == 2) ? a_off.z : a_off.w;
    const long co = (z == 0) ? c_off.x : (z == 1) ? c_off.y : (z == 2) ? c_off.z : c_off.w;
    const long eo = (z == 0) ? ep_off.x : (z == 1) ? ep_off.y : (z == 2) ? ep_off.z : ep_off.w;
    const float* A = A_base + ao;
    float* C = C_base + co;
    const int bm = blockIdx.y * 128;
    const int bn = blockIdx.x * 128;
    const int warp_m = (wid & 3) * 32;
    const int warp_n = (wid >> 2) * 64;
    const uint32_t smem_u = (uint32_t)__cvta_generic_to_shared(sm);

    if (SCALE_A && tid < 128) s_cs[tid] = cs_base[z * 128 + tid];

    float acc[2][8][4];
    #pragma unroll
    for (int i = 0; i < 2; i++)
        #pragma unroll
        for (int j = 0; j < 8; j++)
            #pragma unroll
            for (int q = 0; q < 4; q++) acc[i][j][q] = 0.0f;

    auto load_stage = [&](int st, int k0) {
        #pragma unroll
        for (int i = 0; i < 4; i++) {
            int id = tid + i * 256;
            int m = id >> 3, c = id & 7;
            cp16(smem_u + (uint32_t)(st * 4608 + m * 36 + c * 4) * 4,
                 A + (size_t)(bm + m) * K + k0 + c * 4);
        }
        if (TRANSB) {
            #pragma unroll
            for (int i = 0; i < 4; i++) {
                int id = tid + i * 256;
                int n = id >> 3, c = id & 7;
                cp16(smem_u + (uint32_t)(9216 + st * 4608 + n * 36 + c * 4) * 4,
                     Bm + (size_t)(bn + n) * K + k0 + c * 4);
            }
        } else {
            #pragma unroll
            for (int i = 0; i < 4; i++) {
                int id = tid + i * 256;
                int k = id >> 5, c = id & 31;
                cp16(smem_u + (uint32_t)(9216 + st * 4352 + k * 136 + c * 4) * 4,
                     Bm + (size_t)(k0 + k) * N + bn + c * 4);
            }
        }
    };

    const int r0 = lane >> 2, c0 = lane & 3;
    const int nk = K >> 5;

    load_stage(0, 0);
    asm volatile("cp.async.commit_group;");

    for (int kt = 0; kt < nk; kt++) {
        const int cur = kt & 1;
        const int k0g = kt << 5;
        if (kt + 1 < nk) {
            load_stage((kt + 1) & 1, (kt + 1) << 5);
            asm volatile("cp.async.commit_group;");
            asm volatile("cp.async.wait_group 1;");
        } else {
            asm volatile("cp.async.wait_group 0;");
        }
        __syncthreads();

        #pragma unroll
        for (int ks = 0; ks < 32; ks += 8) {
            uint32_t a[2][4], b[8][2];
            float cs0 = 1.0f, cs1 = 1.0f;
            if (SCALE_A) { cs0 = s_cs[k0g + ks + c0]; cs1 = s_cs[k0g + ks + 4 + c0]; }
            #pragma unroll
            for (int fm = 0; fm < 2; fm++) {
                int mb = warp_m + fm * 16;
                const uint32_t* Ab = sm + cur * 4608;
                float v0 = __uint_as_float(Ab[(mb + r0) * 36 + ks + c0]);
                float v1 = __uint_as_float(Ab[(mb + 8 + r0) * 36 + ks + c0]);
                float v2 = __uint_as_float(Ab[(mb + r0) * 36 + ks + 4 + c0]);
                float v3 = __uint_as_float(Ab[(mb + 8 + r0) * 36 + ks + 4 + c0]);
                if (SCALE_A) { v0 *= cs0; v1 *= cs0; v2 *= cs1; v3 *= cs1; }
                a[fm][0] = f2tf(v0); a[fm][1] = f2tf(v1);
                a[fm][2] = f2tf(v2); a[fm][3] = f2tf(v3);
            }
            if (TRANSB) {
                const uint32_t* Bb = sm + 9216 + cur * 4608;
                #pragma unroll
                for (int fn = 0; fn < 8; fn++) {
                    int nb = warp_n + fn * 8 + r0;
                    b[fn][0] = f2tf(__uint_as_float(Bb[nb * 36 + ks + c0]));
                    b[fn][1] = f2tf(__uint_as_float(Bb[nb * 36 + ks + 4 + c0]));
                }
            } else {
                const uint32_t* Bb = sm + 9216 + cur * 4352;
                #pragma unroll
                for (int fn = 0; fn < 8; fn++) {
                    int nb = warp_n + fn * 8 + r0;
                    b[fn][0] = f2tf(__uint_as_float(Bb[(ks + c0) * 136 + nb]));
                    b[fn][1] = f2tf(__uint_as_float(Bb[(ks + 4 + c0) * 136 + nb]));
                }
            }
            #pragma unroll
            for (int fm = 0; fm < 2; fm++)
                #pragma unroll
                for (int fn = 0; fn < 8; fn++)
                    mma_tf32(acc[fm][fn], a[fm], b[fn]);
        }
        __syncthreads();
    }

    // ---- epilogue ----
    const int cc = (lane & 3) * 2;
    float alpha = 0.f, oma = 0.f;
    if (EPI == 1) { alpha = alphas[z]; oma = 1.0f - alpha; }
    const float* EP = (EPI != 0) ? (ep_base + (EPI == 1 ? eo : 0)) : nullptr;
    float score_local = 0.0f;

    #pragma unroll
    for (int fm = 0; fm < 2; fm++) {
        #pragma unroll
        for (int fn = 0; fn < 8; fn++) {
            int row = bm + warp_m + fm * 16 + r0;
            int col = bn + warp_n + fn * 8 + cc;
            float b0 = BIAS ? bias[col] : 0.0f;
            float b1 = BIAS ? bias[col + 1] : 0.0f;
            float v00 = acc[fm][fn][0] + b0, v01 = acc[fm][fn][1] + b1;
            float v10 = acc[fm][fn][2] + b0, v11 = acc[fm][fn][3] + b1;
            if (EPI == 0) {
                if (row < M)     *(float2*)(C + (size_t)row * N + col)       = make_float2(v00, v01);
                if (row + 8 < M) *(float2*)(C + (size_t)(row + 8) * N + col) = make_float2(v10, v11);
            } else if (EPI == 1) {
                if (row < M) {
                    float2 s = *(const float2*)(EP + (size_t)row * N + col);
                    *(float2*)(C + (size_t)row * N + col) =
                        make_float2(v00 * alpha + oma * s.x, v01 * alpha + oma * s.y);
                }
                if (row + 8 < M) {
                    float2 s = *(const float2*)(EP + (size_t)(row + 8) * N + col);
                    *(float2*)(C + (size_t)(row + 8) * N + col) =
                        make_float2(v10 * alpha + oma * s.x, v11 * alpha + oma * s.y);
                }
            } else {
                float q0 = EP[col], q1 = EP[col + 1];
                if (row < M) {
                    float l0 = v00 > 0.f ? v00 : 0.01f * v00;
                    float l1 = v01 > 0.f ? v01 : 0.01f * v01;
                    score_local += l0 * q0 + l1 * q1;
                }
                if (row + 8 < M) {
                    float l0 = v10 > 0.f ? v10 : 0.01f * v10;
                    float l1 = v11 > 0.f ? v11 : 0.01f * v11;
                    score_local += l0 * q0 + l1 * q1;
                }
            }
        }
    }

    if (EPI == 2) {
        __shared__ float sred[8];
        #pragma unroll
        for (int o = 16; o > 0; o >>= 1)
            score_local += __shfl_xor_sync(0xFFFFFFFFu, score_local, o);
        if (lane == 0) sred[wid] = score_local;
        __syncthreads();
        if (tid == 0) {
            float tot = 0.f;
            #pragma unroll
            for (int w = 0; w < 8; w++) tot += sred[w];
            atomicAdd(&scores[z], (double)tot);
        }
    }
}

// ---------------- CSR aggregation: persistent warps, 4-way unroll, fused BN stats ----
template <bool STATS>
__global__ void k_agg(const float* __restrict__ bias, int Nn) {
    int r = blockIdx.y;
    int lane = threadIdx.x & 31;
    int warp0 = blockIdx.x * (blockDim.x >> 5) + (threadIdx.x >> 5);
    int nwarps = gridDim.x * (blockDim.x >> 5);
    const float* h = g_h[r];
    const int* csr_src = g_csr_src[r];
    const float* csr_c = g_csr_c[r];
    float4 bv = ((const float4*)bias)[lane];

    double s0 = 0, s1 = 0, s2 = 0, s3 = 0;
    double q0 = 0, q1 = 0, q2 = 0, q3 = 0;

    for (int d = warp0; d < Nn; d += nwarps) {
        float di = g_dinv[r][d];
        float d2 = di * di;
        float4 acc = ((const float4*)(h + (size_t)d * D))[lane];
        acc.x = acc.x * d2 + bv.x;
        acc.y = acc.y * d2 + bv.y;
        acc.z = acc.z * d2 + bv.z;
        acc.w = acc.w * d2 + bv.w;
        int beg = g_rowptr[r][d], end = g_rowptr[r][d + 1];
        int e = beg;
        int end4 = beg + ((end - beg) & ~3);
        for (; e < end4; e += 4) {
            int sA = csr_src[e], sB = csr_src[e + 1], sC = csr_src[e + 2], sD = csr_src[e + 3];
            float cA = csr_c[e], cB = csr_c[e + 1], cC = csr_c[e + 2], cD = csr_c[e + 3];
            float4 hA = ((const float4*)(h + (size_t)sA * D))[lane];
            float4 hB = ((const float4*)(h + (size_t)sB * D))[lane];
            float4 hC = ((const float4*)(h + (size_t)sC * D))[lane];
            float4 hD = ((const float4*)(h + (size_t)sD * D))[lane];
            acc.x += hA.x * cA + hB.x * cB + hC.x * cC + hD.x * cD;
            acc.y += hA.y * cA + hB.y * cB + hC.y * cC + hD.y * cD;
            acc.z += hA.z * cA + hB.z * cB + hC.z * cC + hD.z * cD;
            acc.w += hA.w * cA + hB.w * cB + hC.w * cC + hD.w * cD;
        }
        for (; e < end; e++) {
            int s = csr_src[e];
            float c = csr_c[e];
            float4 hv = ((const float4*)(h + (size_t)s * D))[lane];
            acc.x += hv.x * c;
            acc.y += hv.y * c;
            acc.z += hv.z * c;
            acc.w += hv.w * c;
        }
        ((float4*)(g_agg[r] + (size_t)d * D))[lane] = acc;
        if (STATS) {
            s0 += acc.x; q0 += (double)acc.x * acc.x;
            s1 += acc.y; q1 += (double)acc.y * acc.y;
            s2 += acc.z; q2 += (double)acc.z * acc.z;
            s3 += acc.w; q3 += (double)acc.w * acc.w;
        }
    }

    if (STATS) {
        __shared__ double ssum[128], ssq[128];
        for (int t = threadIdx.x; t < 128; t += blockDim.x) { ssum[t] = 0.0; ssq[t] = 0.0; }
        __syncthreads();
        int c4 = lane * 4;
        atomicAdd(&ssum[c4 + 0], s0); atomicAdd(&ssq[c4 + 0], q0);
        atomicAdd(&ssum[c4 + 1], s1); atomicAdd(&ssq[c4 + 1], q1);
        atomicAdd(&ssum[c4 + 2], s2); atomicAdd(&ssq[c4 + 2], q2);
        atomicAdd(&ssum[c4 + 3], s3); atomicAdd(&ssq[c4 + 3], q3);
        __syncthreads();
        for (int t = threadIdx.x; t < 128; t += blockDim.x) {
            atomicAdd(&g_sum[r][t], ssum[t]);
            atomicAdd(&g_sumsq[r][t], ssq[t]);
        }
    }
}

// ---------------- BatchNorm finalize (re-zeros stats for the next layer) ----------------
__global__ void k_bn_final(const float* __restrict__ gamma, const float* __restrict__ beta, int Nn) {
    int t = threadIdx.x;   // 512
    int r = t >> 7, j = t & 127;
    double mean = g_sum[r][j] / Nn;
    double var = g_sumsq[r][j] / Nn - mean * mean;
    float sc = gamma[j] * (float)(1.0 / sqrt(var + 1e-5));
    g_scale[r][j] = sc;
    g_shift[r][j] = beta[j] - (float)mean * sc;
    g_sum[r][j] = 0.0;
    g_sumsq[r][j] = 0.0;
}

// emb[r] = base + lrelu(agg*scale+shift); base = features (layer0) or emb[r]
__global__ void k_bn_apply(const float* __restrict__ base, int Nn) {   // grid (g4, 4) x 256
    int r = blockIdx.y;
    size_t i4 = (size_t)blockIdx.x * blockDim.x + threadIdx.x;
    if (i4 >= (size_t)Nn * 32) return;
    int c4 = (int)(i4 & 31) * 4;
    float4 a = ((const float4*)g_agg[r])[i4];
    float4 sc = *(const float4*)(g_scale[r] + c4);
    float4 sh = *(const float4*)(g_shift[r] + c4);
    float4 v;
    v.x = a.x * sc.x + sh.x; v.x = v.x > 0.f ? v.x : 0.01f * v.x;
    v.y = a.y * sc.y + sh.y; v.y = v.y > 0.f ? v.y : 0.01f * v.y;
    v.z = a.z * sc.z + sh.z; v.z = v.z > 0.f ? v.z : 0.01f * v.z;
    v.w = a.w * sc.w + sh.w; v.w = v.w > 0.f ? v.w : 0.01f * v.w;
    float4 b = base ? ((const float4*)base)[i4] : ((const float4*)g_emb[r])[i4];
    v.x += b.x; v.y += b.y; v.z += b.z; v.w += b.w;
    ((float4*)g_emb[r])[i4] = v;
}

// ---------------- rels update ----------------
__global__ void k_rels_update(const float* __restrict__ Wrt, const float* __restrict__ brt) {
    __shared__ float cur[4 * D];
    int t = threadIdx.x;  // 512
    cur[t] = ((float*)g_rels)[t];
    __syncthreads();
    int r = t >> 7, j = t & 127;
    float s = brt[j];
    #pragma unroll 8
    for (int k = 0; k < D; k++) s = fmaf(cur[r * D + k], Wrt[j * D + k], s);
    ((float*)g_rels)[t] = s;
}

// ---------------- attention ----------------
__global__ void k_attn(int Nn) {
    int gw = (blockIdx.x * blockDim.x + threadIdx.x) >> 5;
    int lane = threadIdx.x & 31;
    if (gw >= Nn * 4) return;
    int n = gw >> 2, h = gw & 3;
    float q[4], kk[4], v[4];
    #pragma unroll
    for (int l = 0; l < 4; l++) {
        const float* base = g_qkv[l] + (size_t)n * 384 + h * 32 + lane;
        q[l]  = base[0] * 0.17677669529663687f;
        kk[l] = base[128];
        v[l]  = base[256];
    }
    float sc[4][4];
    #pragma unroll
    for (int l = 0; l < 4; l++)
        #pragma unroll
        for (int m = 0; m < 4; m++) {
            float p = q[l] * kk[m];
            p += __shfl_xor_sync(0xFFFFFFFFu, p, 16);
            p += __shfl_xor_sync(0xFFFFFFFFu, p, 8);
            p += __shfl_xor_sync(0xFFFFFFFFu, p, 4);
            p += __shfl_xor_sync(0xFFFFFFFFu, p, 2);
            p += __shfl_xor_sync(0xFFFFFFFFu, p, 1);
            sc[l][m] = p;
        }
    #pragma unroll
    for (int l = 0; l < 4; l++) {
        float mx = fmaxf(fmaxf(sc[l][0], sc[l][1]), fmaxf(sc[l][2], sc[l][3]));
        float e0 = expf(sc[l][0] - mx), e1 = expf(sc[l][1] - mx);
        float e2 = expf(sc[l][2] - mx), e3 = expf(sc[l][3] - mx);
        float inv = 1.0f / (e0 + e1 + e2 + e3);
        float o = (e0 * v[0] + e1 * v[1] + e2 * v[2] + e3 * v[3]) * inv;
        g_h[l][(size_t)n * D + h * 32 + lane] = o;
    }
}

// ---------------- final outputs (float4; coef computed inline per block) ----------------
__global__ void k_final(float* __restrict__ out, int Nn) {
    __shared__ float sco[4];
    if (threadIdx.x == 0) {
        double sv[4] = { g_scores[0] / Nn, g_scores[1] / Nn, g_scores[3] / Nn, g_scores[2] / Nn };
        double mx = sv[0];
        for (int i = 1; i < 4; i++) mx = sv[i] > mx ? sv[i] : mx;
        double e[4], ss = 0.0;
        for (int i = 0; i < 4; i++) { e[i] = exp(sv[i] - mx); ss += e[i]; }
        double w[4];
        for (int i = 0; i < 4; i++) w[i] = e[i] / ss;
        sco[0] = (float)w[0];
        sco[1] = (float)w[1];
        sco[2] = (float)w[3];
        sco[3] = (float)w[2];
    }
    __syncthreads();
    size_t i4 = (size_t)blockIdx.x * blockDim.x + threadIdx.x;
    size_t ND4 = (size_t)Nn * 32;
    if (i4 >= ND4) return;
    int c4 = (int)(i4 & 31) * 4;
    float4 e0 = ((const float4*)g_emb[0])[i4];
    float4 e1 = ((const float4*)g_emb[1])[i4];
    float4 e2 = ((const float4*)g_emb[2])[i4];
    float4 e3 = ((const float4*)g_emb[3])[i4];
    float w0 = sco[0], w1 = sco[1], w2 = sco[2], w3 = sco[3];
    float4 r4;
    r4.x = w0 * e0.x + w1 * e1.x + w2 * e2.x + w3 * e3.x;
    r4.y = w0 * e0.y + w1 * e1.y + w2 * e2.y + w3 * e3.y;
    r4.z = w0 * e0.z + w1 * e1.z + w2 * e2.z + w3 * e3.z;
    r4.w = w0 * e0.w + w1 * e1.w + w2 * e2.w + w3 * e3.w;
    float4* o4 = (float4*)out;
    o4[i4] = r4;
    float4 c;
    c = *(const float4*)(g_rels[3] + c4);
    o4[ND4 + i4]     = make_float4(r4.x * c.x, r4.y * c.y, r4.z * c.z, r4.w * c.w);
    c = *(const float4*)(g_rels[0] + c4);
    o4[2 * ND4 + i4] = make_float4(r4.x * c.x, r4.y * c.y, r4.z * c.z, r4.w * c.w);
    c = *(const float4*)(g_rels[1] + c4);
    o4[3 * ND4 + i4] = make_float4(r4.x * c.x, r4.y * c.y, r4.z * c.z, r4.w * c.w);
    c = *(const float4*)(g_rels[2] + c4);
    o4[4 * ND4 + i4] = make_float4(r4.x * c.x, r4.y * c.y, r4.z * c.z, r4.w * c.w);
}

// ---------------- host orchestration ----------------
extern "C" void kernel_launch(void* const* d_in, const int* in_sizes, int n_in,
                              void* d_out, int out_size) {
    const float* features   = (const float*)d_in[0];
    const float* rel_emb    = (const float*)d_in[1];
    const int*   edge_index = (const int*)  d_in[2];
    const float* W_gcn      = (const float*)d_in[3];
    const float* b_gcn      = (const float*)d_in[4];
    const float* bn_gamma   = (const float*)d_in[5];
    const float* bn_beta    = (const float*)d_in[6];
    const float* W_rt       = (const float*)d_in[7];
    const float* b_rt       = (const float*)d_in[8];
    const float* attn_w_in  = (const float*)d_in[9];
    const float* attn_b_in  = (const float*)d_in[10];
    const float* attn_w_out = (const float*)d_in[11];
    const float* attn_b_out = (const float*)d_in[12];
    const float* alphas     = (const float*)d_in[13];
    const float* fusion_q   = (const float*)d_in[14];
    const float* fusion_w   = (const float*)d_in[15];
    const float* fusion_b   = (const float*)d_in[16];

    int Nn = in_sizes[0] / D;
    int E  = in_sizes[2] / 8;
    if (Nn > MAXN || E > EMAX) return;

    static float *emb = nullptr, *h, *agg, *qkv, *rels;
    static double *scores;
    static bool attr_done = false;
    if (!emb) {
        cudaGetSymbolAddress((void**)&emb,    g_emb);
        cudaGetSymbolAddress((void**)&h,      g_h);
        cudaGetSymbolAddress((void**)&agg,    g_agg);
        cudaGetSymbolAddress((void**)&qkv,    g_qkv);
        cudaGetSymbolAddress((void**)&rels,   g_rels);
        cudaGetSymbolAddress((void**)&scores, g_scores);
    }
    const int SMEM_T  = 73728;
    const int SMEM_NT = 71680;
    if (!attr_done) {
        cudaFuncSetAttribute((const void*)k_gemm_tf32<false, true,  false, 0>,
                             cudaFuncAttributeMaxDynamicSharedMemorySize, SMEM_NT);
        cudaFuncSetAttribute((const void*)k_gemm_tf32<true,  false, true,  0>,
                             cudaFuncAttributeMaxDynamicSharedMemorySize, SMEM_T);
        cudaFuncSetAttribute((const void*)k_gemm_tf32<true,  false, true,  1>,
                             cudaFuncAttributeMaxDynamicSharedMemorySize, SMEM_T);
        cudaFuncSetAttribute((const void*)k_gemm_tf32<true,  false, true,  2>,
                             cudaFuncAttributeMaxDynamicSharedMemorySize, SMEM_T);
        attr_done = true;
    }

    const long S = (long)MAXN * D;
    const long Q = (long)MAXN * 384;
    const long4 ident = make_long4(0, S, 2 * S, 3 * S);
    const long4 smapo = make_long4(3 * S, 0, 2 * S, 1 * S);
    const long4 qoff  = make_long4(0, Q, 2 * Q, 3 * Q);
    const long4 zero4 = make_long4(0, 0, 0, 0);

    size_t ND = (size_t)Nn * D;
    int gElem = (int)((ND + TPB - 1) / TPB);
    int g4    = (int)(((size_t)Nn * 32 + TPB - 1) / TPB);
    int gEdge = (E + TPB - 1) / TPB;
    int gy    = (Nn + 127) / 128;
    int nb    = (Nn + 1023) / 1024;
    int gTail = (int)(((size_t)(MAXN - Nn) * D + TPB - 1) / TPB);

    k_init<<<gElem, TPB>>>(features, rel_emb, Nn);
    if (gTail > 0) k_zero_tail<<<gTail, TPB>>>(Nn);
    k_hist<<<dim3(gEdge, 4), TPB>>>(edge_index, E);
    k_scan1<<<dim3(nb, 4), 1024>>>(Nn);
    k_scan2<<<4, 64>>>(nb);
    k_scan3<<<dim3(nb, 4), 1024>>>(Nn);
    k_fill<<<dim3(gEdge, 4), TPB>>>(edge_index, E);

    for (int i = 0; i < 3; i++) {
        const float* Wg = W_gcn + (size_t)i * D * D;
        const float* bg = b_gcn + (size_t)i * D;
        // h[r] = (emb_src * rels[r]) @ Wg ; layer 0 reads emb[0] (features) for all r
        k_gemm_tf32<false, true, false, 0><<<dim3(1, gy, 4), 256, SMEM_NT>>>(
            emb, (i == 0) ? zero4 : ident, Wg, h, ident, Nn, D, D,
            rels, nullptr, nullptr, zero4, nullptr, nullptr);
        if (i < 2) {
            k_agg<true><<<dim3(624, 4), TPB>>>(bg, Nn);
            k_bn_final<<<1, 512>>>(bn_gamma + (size_t)i * D, bn_beta + (size_t)i * D, Nn);
            k_bn_apply<<<dim3(g4, 4), TPB>>>((i == 0) ? features : nullptr, Nn);
        } else {
            k_agg<false><<<dim3(624, 4), TPB>>>(bg, Nn);
        }
        k_rels_update<<<1, 512>>>(W_rt + (size_t)i * D * D, b_rt + (size_t)i * D);
    }

    // QKV over stk[l] = agg[SMAP[l]]
    k_gemm_tf32<true, false, true, 0><<<dim3(3, gy, 4), 256, SMEM_T>>>(
        agg, smapo, attn_w_in, qkv, qoff, Nn, 384, D,
        nullptr, attn_b_in, nullptr, zero4, nullptr, nullptr);
    k_attn<<<(int)(((size_t)Nn * 128 + TPB - 1) / TPB), TPB>>>(Nn);
    // out-proj + fused blend -> emb[l]
    k_gemm_tf32<true, false, true, 1><<<dim3(1, gy, 4), 256, SMEM_T>>>(
        h, ident, attn_w_out, emb, ident, Nn, D, D,
        nullptr, attn_b_out, agg, smapo, alphas, nullptr);
    // fused score GEMMs
    k_gemm_tf32<true, false, true, 2><<<dim3(1, gy, 4), 256, SMEM_T>>>(
        emb, ident, fusion_w, h, ident, Nn, D, D,
        nullptr, fusion_b, fusion_q, zero4, nullptr, scores);
    k_final<<<g4, TPB>>>((float*)d_out, Nn);
}

// round 13
// speedup vs baseline: 1.2944x; 1.0958x over previous
#include <cuda_runtime.h>
#include <math.h>
#include <stdint.h>

#define D 128
#define MAXN 50048           // 391 * 128, multiple of 128
#define EMAX 409600
#define TPB 256

// ---------------- scratch (static device globals; no allocations) ----------------
__device__ __align__(16) float g_emb[4][(size_t)MAXN * D];
__device__ __align__(16) float g_h  [4][(size_t)MAXN * D];
__device__ __align__(16) float g_agg[4][(size_t)MAXN * D];
__device__ __align__(16) float g_qkv[4][(size_t)MAXN * 384];
__device__ int   g_cnt   [4][MAXN];
__device__ int   g_rowptr[4][MAXN + 1];
__device__ int   g_wofs  [4][MAXN];
__device__ int   g_psum  [4][64];
__device__ int   g_total [4];
__device__ int   g_csr_src[4][EMAX];
__device__ float g_csr_c [4][EMAX];
__device__ __align__(16) float g_dinv[4][MAXN];
__device__ __align__(16) float g_rels[4][D];
__device__ double g_sum[4][D];
__device__ double g_sumsq[4][D];
__device__ __align__(16) float g_scale[4][D];
__device__ __align__(16) float g_shift[4][D];
__device__ double g_scores[4];

// ---------------- helpers ----------------
__device__ __forceinline__ uint32_t f2tf(float x) {
    uint32_t u;
    asm("cvt.rna.tf32.f32 %0, %1;" : "=r"(u) : "f"(x));
    return u;
}
__device__ __forceinline__ void mma_tf32(float* c, const uint32_t* a, const uint32_t* b) {
    asm volatile(
        "mma.sync.aligned.m16n8k8.row.col.f32.tf32.tf32.f32 "
        "{%0,%1,%2,%3}, {%4,%5,%6,%7}, {%8,%9}, {%0,%1,%2,%3};"
        : "+f"(c[0]), "+f"(c[1]), "+f"(c[2]), "+f"(c[3])
        : "r"(a[0]), "r"(a[1]), "r"(a[2]), "r"(a[3]), "r"(b[0]), "r"(b[1]));
}
__device__ __forceinline__ void cp16(uint32_t dst, const void* src) {
    asm volatile("cp.async.cg.shared.global [%0], [%1], 16;" :: "r"(dst), "l"(src));
}

// ---------------- init: emb[0] = features; permute rels; zero stats/scores ----------
__global__ void k_init(const float* __restrict__ feat, const float* __restrict__ rel_emb, int Nn) {
    size_t idx = (size_t)blockIdx.x * blockDim.x + threadIdx.x;
    size_t tot = (size_t)Nn * D;
    if (idx < tot) {
        g_emb[0][idx] = feat[idx];
    }
    if (idx < 4 * D) {
        const int perm[4] = {3, 0, 1, 2};
        int r = (int)(idx / D), j = (int)(idx % D);
        g_rels[r][j] = rel_emb[perm[r] * D + j];
        ((double*)g_sum)[idx] = 0.0;
        ((double*)g_sumsq)[idx] = 0.0;
    }
    if (idx < 4) g_scores[idx] = 0.0;
}

// zero scratch tail rows [Nn, MAXN) so GEMM A-cp.async loads need no bounds checks
__global__ void k_zero_tail(int Nn) {
    size_t tail = (size_t)(MAXN - Nn) * D;
    size_t idx = (size_t)blockIdx.x * blockDim.x + threadIdx.x;
    if (idx >= tail) return;
    size_t o = (size_t)Nn * D + idx;
    #pragma unroll
    for (int r = 0; r < 4; r++) { g_emb[r][o] = 0.f; g_h[r][o] = 0.f; g_agg[r][o] = 0.f; }
}

// ---------------- CSR build (side stream) ----------------
__global__ void k_zero_cnt() {
    size_t idx = (size_t)blockIdx.x * blockDim.x + threadIdx.x;
    if (idx < 4 * (size_t)MAXN) ((int*)g_cnt)[idx] = 0;
}

__global__ void k_hist(const int* __restrict__ edge, int E) {
    const int perm[4] = {3, 0, 1, 2};
    int r = blockIdx.y;
    const int* dst = edge + ((size_t)perm[r] * 2 + 1) * E;
    int t = blockIdx.x * blockDim.x + threadIdx.x;
    if (t < E) atomicAdd(&g_cnt[r][dst[t]], 1);
}

__global__ void k_scan1(int Nn) {     // grid (nb, 4) x 1024; also computes dinv
    int r = blockIdx.y, t = threadIdx.x;
    int i = blockIdx.x * 1024 + t;
    int v = (i < Nn) ? g_cnt[r][i] : 0;
    if (i < Nn) g_dinv[r][i] = rsqrtf((float)v + 1.0f);
    int x = v;
    #pragma unroll
    for (int o = 1; o < 32; o <<= 1) {
        int y = __shfl_up_sync(0xFFFFFFFFu, x, o);
        if ((t & 31) >= o) x += y;
    }
    __shared__ int ws[32];
    if ((t & 31) == 31) ws[t >> 5] = x;
    __syncthreads();
    if (t < 32) {
        int y = ws[t];
        #pragma unroll
        for (int o = 1; o < 32; o <<= 1) {
            int z = __shfl_up_sync(0xFFFFFFFFu, y, o);
            if (t >= o) y += z;
        }
        ws[t] = y;
    }
    __syncthreads();
    int off = (t >= 32) ? ws[(t >> 5) - 1] : 0;
    int incl = x + off;
    if (i < Nn) g_rowptr[r][i] = incl - v;
    if (t == 1023) g_psum[r][blockIdx.x] = incl;
}

__global__ void k_scan2(int nb) {     // grid 4 x 64
    int r = blockIdx.x, t = threadIdx.x;
    int v = (t < nb) ? g_psum[r][t] : 0;
    int x = v;
    #pragma unroll
    for (int o = 1; o < 32; o <<= 1) {
        int y = __shfl_up_sync(0xFFFFFFFFu, x, o);
        if ((t & 31) >= o) x += y;
    }
    __shared__ int w2[2];
    if ((t & 31) == 31) w2[t >> 5] = x;
    __syncthreads();
    int off = (t >= 32) ? w2[0] : 0;
    int incl = x + off;
    g_psum[r][t] = incl - v;
    if (t == 63) g_total[r] = incl;
}

__global__ void k_scan3(int Nn) {     // grid (nb, 4) x 1024
    int r = blockIdx.y;
    int i = blockIdx.x * 1024 + threadIdx.x;
    if (i < Nn) {
        int val = g_rowptr[r][i] + g_psum[r][blockIdx.x];
        g_rowptr[r][i] = val;
        g_wofs[r][i] = val;
    }
    if (i == 0) g_rowptr[r][Nn] = g_total[r];
}

__global__ void k_fill(const int* __restrict__ edge, int E) {
    const int perm[4] = {3, 0, 1, 2};
    int r = blockIdx.y;
    const int* src = edge + ((size_t)perm[r] * 2) * E;
    const int* dst = src + E;
    int e = blockIdx.x * blockDim.x + threadIdx.x;
    if (e >= E) return;
    int s = src[e], d = dst[e];
    int pos = atomicAdd(&g_wofs[r][d], 1);
    g_csr_src[r][pos] = s;
    g_csr_c[r][pos] = g_dinv[r][s] * g_dinv[r][d];
}

// ---------------- batched pipelined TF32 GEMM ----------------
// BM=128 BN=128 BK=32, 256 threads, cp.async 2-stage double buffer.
// z = blockIdx.z selects batch slice via long4 offsets.
// EPI: 0 plain store (+bias), 1 blend (C = (acc+bias)*alpha[z] + (1-alpha)*stk),
//      2 score (no store; sum lrelu(acc+bias)*q -> scores[z]).
template <bool TRANSB, bool SCALE_A, bool BIAS, int EPI>
__global__ void __launch_bounds__(256) k_gemm_tf32(
    const float* __restrict__ A_base, long4 a_off,
    const float* __restrict__ Bm,
    float* __restrict__ C_base, long4 c_off,
    int M, int N, int K,
    const float* __restrict__ cs_base,
    const float* __restrict__ bias,
    const float* __restrict__ ep_base, long4 ep_off,
    const float* __restrict__ alphas,
    double* __restrict__ scores)
{
    extern __shared__ uint32_t sm[];
    __shared__ float s_cs[128];
    const int tid = threadIdx.x;
    const int lane = tid & 31, wid = tid >> 5;
    const int z = blockIdx.z;
    const long ao = (z == 0) ? a_off.x : (z == 1) ? a_off.y : (z == 2) ? a_off.z : a_off.w;
    const long co = (z == 0) ? c_off.x : (z == 1) ? c_off.y : (z == 2) ? c_off.z : c_off.w;
    const long eo = (z == 0) ? ep_off.x : (z == 1) ? ep_off.y : (z == 2) ? ep_off.z : ep_off.w;
    const float* A = A_base + ao;
    float* C = C_base + co;
    const int bm = blockIdx.y * 128;
    const int bn = blockIdx.x * 128;
    const int warp_m = (wid & 3) * 32;
    const int warp_n = (wid >> 2) * 64;
    const uint32_t smem_u = (uint32_t)__cvta_generic_to_shared(sm);

    if (SCALE_A && tid < 128) s_cs[tid] = cs_base[z * 128 + tid];

    float acc[2][8][4];
    #pragma unroll
    for (int i = 0; i < 2; i++)
        #pragma unroll
        for (int j = 0; j < 8; j++)
            #pragma unroll
            for (int q = 0; q < 4; q++) acc[i][j][q] = 0.0f;

    auto load_stage = [&](int st, int k0) {
        #pragma unroll
        for (int i = 0; i < 4; i++) {
            int id = tid + i * 256;
            int m = id >> 3, c = id & 7;
            cp16(smem_u + (uint32_t)(st * 4608 + m * 36 + c * 4) * 4,
                 A + (size_t)(bm + m) * K + k0 + c * 4);
        }
        if (TRANSB) {
            #pragma unroll
            for (int i = 0; i < 4; i++) {
                int id = tid + i * 256;
                int n = id >> 3, c = id & 7;
                cp16(smem_u + (uint32_t)(9216 + st * 4608 + n * 36 + c * 4) * 4,
                     Bm + (size_t)(bn + n) * K + k0 + c * 4);
            }
        } else {
            #pragma unroll
            for (int i = 0; i < 4; i++) {
                int id = tid + i * 256;
                int k = id >> 5, c = id & 31;
                cp16(smem_u + (uint32_t)(9216 + st * 4352 + k * 136 + c * 4) * 4,
                     Bm + (size_t)(k0 + k) * N + bn + c * 4);
            }
        }
    };

    const int r0 = lane >> 2, c0 = lane & 3;
    const int nk = K >> 5;

    load_stage(0, 0);
    asm volatile("cp.async.commit_group;");

    for (int kt = 0; kt < nk; kt++) {
        const int cur = kt & 1;
        const int k0g = kt << 5;
        if (kt + 1 < nk) {
            load_stage((kt + 1) & 1, (kt + 1) << 5);
            asm volatile("cp.async.commit_group;");
            asm volatile("cp.async.wait_group 1;");
        } else {
            asm volatile("cp.async.wait_group 0;");
        }
        __syncthreads();

        #pragma unroll
        for (int ks = 0; ks < 32; ks += 8) {
            uint32_t a[2][4], b[8][2];
            float cs0 = 1.0f, cs1 = 1.0f;
            if (SCALE_A) { cs0 = s_cs[k0g + ks + c0]; cs1 = s_cs[k0g + ks + 4 + c0]; }
            #pragma unroll
            for (int fm = 0; fm < 2; fm++) {
                int mb = warp_m + fm * 16;
                const uint32_t* Ab = sm + cur * 4608;
                float v0 = __uint_as_float(Ab[(mb + r0) * 36 + ks + c0]);
                float v1 = __uint_as_float(Ab[(mb + 8 + r0) * 36 + ks + c0]);
                float v2 = __uint_as_float(Ab[(mb + r0) * 36 + ks + 4 + c0]);
                float v3 = __uint_as_float(Ab[(mb + 8 + r0) * 36 + ks + 4 + c0]);
                if (SCALE_A) { v0 *= cs0; v1 *= cs0; v2 *= cs1; v3 *= cs1; }
                a[fm][0] = f2tf(v0); a[fm][1] = f2tf(v1);
                a[fm][2] = f2tf(v2); a[fm][3] = f2tf(v3);
            }
            if (TRANSB) {
                const uint32_t* Bb = sm + 9216 + cur * 4608;
                #pragma unroll
                for (int fn = 0; fn < 8; fn++) {
                    int nb = warp_n + fn * 8 + r0;
                    b[fn][0] = f2tf(__uint_as_float(Bb[nb * 36 + ks + c0]));
                    b[fn][1] = f2tf(__uint_as_float(Bb[nb * 36 + ks + 4 + c0]));
                }
            } else {
                const uint32_t* Bb = sm + 9216 + cur * 4352;
                #pragma unroll
                for (int fn = 0; fn < 8; fn++) {
                    int nb = warp_n + fn * 8 + r0;
                    b[fn][0] = f2tf(__uint_as_float(Bb[(ks + c0) * 136 + nb]));
                    b[fn][1] = f2tf(__uint_as_float(Bb[(ks + 4 + c0) * 136 + nb]));
                }
            }
            #pragma unroll
            for (int fm = 0; fm < 2; fm++)
                #pragma unroll
                for (int fn = 0; fn < 8; fn++)
                    mma_tf32(acc[fm][fn], a[fm], b[fn]);
        }
        __syncthreads();
    }

    // ---- epilogue ----
    const int cc = (lane & 3) * 2;
    float alpha = 0.f, oma = 0.f;
    if (EPI == 1) { alpha = alphas[z]; oma = 1.0f - alpha; }
    const float* EP = (EPI != 0) ? (ep_base + (EPI == 1 ? eo : 0)) : nullptr;
    float score_local = 0.0f;

    #pragma unroll
    for (int fm = 0; fm < 2; fm++) {
        #pragma unroll
        for (int fn = 0; fn < 8; fn++) {
            int row = bm + warp_m + fm * 16 + r0;
            int col = bn + warp_n + fn * 8 + cc;
            float b0 = BIAS ? bias[col] : 0.0f;
            float b1 = BIAS ? bias[col + 1] : 0.0f;
            float v00 = acc[fm][fn][0] + b0, v01 = acc[fm][fn][1] + b1;
            float v10 = acc[fm][fn][2] + b0, v11 = acc[fm][fn][3] + b1;
            if (EPI == 0) {
                if (row < M)     *(float2*)(C + (size_t)row * N + col)       = make_float2(v00, v01);
                if (row + 8 < M) *(float2*)(C + (size_t)(row + 8) * N + col) = make_float2(v10, v11);
            } else if (EPI == 1) {
                if (row < M) {
                    float2 s = *(const float2*)(EP + (size_t)row * N + col);
                    *(float2*)(C + (size_t)row * N + col) =
                        make_float2(v00 * alpha + oma * s.x, v01 * alpha + oma * s.y);
                }
                if (row + 8 < M) {
                    float2 s = *(const float2*)(EP + (size_t)(row + 8) * N + col);
                    *(float2*)(C + (size_t)(row + 8) * N + col) =
                        make_float2(v10 * alpha + oma * s.x, v11 * alpha + oma * s.y);
                }
            } else {
                float q0 = EP[col], q1 = EP[col + 1];
                if (row < M) {
                    float l0 = v00 > 0.f ? v00 : 0.01f * v00;
                    float l1 = v01 > 0.f ? v01 : 0.01f * v01;
                    score_local += l0 * q0 + l1 * q1;
                }
                if (row + 8 < M) {
                    float l0 = v10 > 0.f ? v10 : 0.01f * v10;
                    float l1 = v11 > 0.f ? v11 : 0.01f * v11;
                    score_local += l0 * q0 + l1 * q1;
                }
            }
        }
    }

    if (EPI == 2) {
        __shared__ float sred[8];
        #pragma unroll
        for (int o = 16; o > 0; o >>= 1)
            score_local += __shfl_xor_sync(0xFFFFFFFFu, score_local, o);
        if (lane == 0) sred[wid] = score_local;
        __syncthreads();
        if (tid == 0) {
            float tot = 0.f;
            #pragma unroll
            for (int w = 0; w < 8; w++) tot += sred[w];
            atomicAdd(&scores[z], (double)tot);
        }
    }
}

// ---------------- CSR aggregation: persistent warps, 4-way unroll, fused BN stats ----
template <bool STATS>
__global__ void k_agg(const float* __restrict__ bias, int Nn) {
    int r = blockIdx.y;
    int lane = threadIdx.x & 31;
    int warp0 = blockIdx.x * (blockDim.x >> 5) + (threadIdx.x >> 5);
    int nwarps = gridDim.x * (blockDim.x >> 5);
    const float* h = g_h[r];
    const int* csr_src = g_csr_src[r];
    const float* csr_c = g_csr_c[r];
    float4 bv = ((const float4*)bias)[lane];

    double s0 = 0, s1 = 0, s2 = 0, s3 = 0;
    double q0 = 0, q1 = 0, q2 = 0, q3 = 0;

    for (int d = warp0; d < Nn; d += nwarps) {
        float di = g_dinv[r][d];
        float d2 = di * di;
        float4 acc = ((const float4*)(h + (size_t)d * D))[lane];
        acc.x = acc.x * d2 + bv.x;
        acc.y = acc.y * d2 + bv.y;
        acc.z = acc.z * d2 + bv.z;
        acc.w = acc.w * d2 + bv.w;
        int beg = g_rowptr[r][d], end = g_rowptr[r][d + 1];
        int e = beg;
        int end4 = beg + ((end - beg) & ~3);
        for (; e < end4; e += 4) {
            int sA = csr_src[e], sB = csr_src[e + 1], sC = csr_src[e + 2], sD = csr_src[e + 3];
            float cA = csr_c[e], cB = csr_c[e + 1], cC = csr_c[e + 2], cD = csr_c[e + 3];
            float4 hA = ((const float4*)(h + (size_t)sA * D))[lane];
            float4 hB = ((const float4*)(h + (size_t)sB * D))[lane];
            float4 hC = ((const float4*)(h + (size_t)sC * D))[lane];
            float4 hD = ((const float4*)(h + (size_t)sD * D))[lane];
            acc.x += hA.x * cA + hB.x * cB + hC.x * cC + hD.x * cD;
            acc.y += hA.y * cA + hB.y * cB + hC.y * cC + hD.y * cD;
            acc.z += hA.z * cA + hB.z * cB + hC.z * cC + hD.z * cD;
            acc.w += hA.w * cA + hB.w * cB + hC.w * cC + hD.w * cD;
        }
        for (; e < end; e++) {
            int s = csr_src[e];
            float c = csr_c[e];
            float4 hv = ((const float4*)(h + (size_t)s * D))[lane];
            acc.x += hv.x * c;
            acc.y += hv.y * c;
            acc.z += hv.z * c;
            acc.w += hv.w * c;
        }
        ((float4*)(g_agg[r] + (size_t)d * D))[lane] = acc;
        if (STATS) {
            s0 += acc.x; q0 += (double)acc.x * acc.x;
            s1 += acc.y; q1 += (double)acc.y * acc.y;
            s2 += acc.z; q2 += (double)acc.z * acc.z;
            s3 += acc.w; q3 += (double)acc.w * acc.w;
        }
    }

    if (STATS) {
        __shared__ double ssum[128], ssq[128];
        for (int t = threadIdx.x; t < 128; t += blockDim.x) { ssum[t] = 0.0; ssq[t] = 0.0; }
        __syncthreads();
        int c4 = lane * 4;
        atomicAdd(&ssum[c4 + 0], s0); atomicAdd(&ssq[c4 + 0], q0);
        atomicAdd(&ssum[c4 + 1], s1); atomicAdd(&ssq[c4 + 1], q1);
        atomicAdd(&ssum[c4 + 2], s2); atomicAdd(&ssq[c4 + 2], q2);
        atomicAdd(&ssum[c4 + 3], s3); atomicAdd(&ssq[c4 + 3], q3);
        __syncthreads();
        for (int t = threadIdx.x; t < 128; t += blockDim.x) {
            atomicAdd(&g_sum[r][t], ssum[t]);
            atomicAdd(&g_sumsq[r][t], ssq[t]);
        }
    }
}

// ---------------- BatchNorm finalize (re-zeros stats for the next layer) ----------------
__global__ void k_bn_final(const float* __restrict__ gamma, const float* __restrict__ beta, int Nn) {
    int t = threadIdx.x;   // 512
    int r = t >> 7, j = t & 127;
    double mean = g_sum[r][j] / Nn;
    double var = g_sumsq[r][j] / Nn - mean * mean;
    float sc = gamma[j] * (float)(1.0 / sqrt(var + 1e-5));
    g_scale[r][j] = sc;
    g_shift[r][j] = beta[j] - (float)mean * sc;
    g_sum[r][j] = 0.0;
    g_sumsq[r][j] = 0.0;
}

// emb[r] = base + lrelu(agg*scale+shift); base = features (layer0) or emb[r]
__global__ void k_bn_apply(const float* __restrict__ base, int Nn) {   // grid (g4, 4) x 256
    int r = blockIdx.y;
    size_t i4 = (size_t)blockIdx.x * blockDim.x + threadIdx.x;
    if (i4 >= (size_t)Nn * 32) return;
    int c4 = (int)(i4 & 31) * 4;
    float4 a = ((const float4*)g_agg[r])[i4];
    float4 sc = *(const float4*)(g_scale[r] + c4);
    float4 sh = *(const float4*)(g_shift[r] + c4);
    float4 v;
    v.x = a.x * sc.x + sh.x; v.x = v.x > 0.f ? v.x : 0.01f * v.x;
    v.y = a.y * sc.y + sh.y; v.y = v.y > 0.f ? v.y : 0.01f * v.y;
    v.z = a.z * sc.z + sh.z; v.z = v.z > 0.f ? v.z : 0.01f * v.z;
    v.w = a.w * sc.w + sh.w; v.w = v.w > 0.f ? v.w : 0.01f * v.w;
    float4 b = base ? ((const float4*)base)[i4] : ((const float4*)g_emb[r])[i4];
    v.x += b.x; v.y += b.y; v.z += b.z; v.w += b.w;
    ((float4*)g_emb[r])[i4] = v;
}

// ---------------- rels update ----------------
__global__ void k_rels_update(const float* __restrict__ Wrt, const float* __restrict__ brt) {
    __shared__ float cur[4 * D];
    int t = threadIdx.x;  // 512
    cur[t] = ((float*)g_rels)[t];
    __syncthreads();
    int r = t >> 7, j = t & 127;
    float s = brt[j];
    #pragma unroll 8
    for (int k = 0; k < D; k++) s = fmaf(cur[r * D + k], Wrt[j * D + k], s);
    ((float*)g_rels)[t] = s;
}

// ---------------- attention ----------------
__global__ void k_attn(int Nn) {
    int gw = (blockIdx.x * blockDim.x + threadIdx.x) >> 5;
    int lane = threadIdx.x & 31;
    if (gw >= Nn * 4) return;
    int n = gw >> 2, h = gw & 3;
    float q[4], kk[4], v[4];
    #pragma unroll
    for (int l = 0; l < 4; l++) {
        const float* base = g_qkv[l] + (size_t)n * 384 + h * 32 + lane;
        q[l]  = base[0] * 0.17677669529663687f;
        kk[l] = base[128];
        v[l]  = base[256];
    }
    float sc[4][4];
    #pragma unroll
    for (int l = 0; l < 4; l++)
        #pragma unroll
        for (int m = 0; m < 4; m++) {
            float p = q[l] * kk[m];
            p += __shfl_xor_sync(0xFFFFFFFFu, p, 16);
            p += __shfl_xor_sync(0xFFFFFFFFu, p, 8);
            p += __shfl_xor_sync(0xFFFFFFFFu, p, 4);
            p += __shfl_xor_sync(0xFFFFFFFFu, p, 2);
            p += __shfl_xor_sync(0xFFFFFFFFu, p, 1);
            sc[l][m] = p;
        }
    #pragma unroll
    for (int l = 0; l < 4; l++) {
        float mx = fmaxf(fmaxf(sc[l][0], sc[l][1]), fmaxf(sc[l][2], sc[l][3]));
        float e0 = expf(sc[l][0] - mx), e1 = expf(sc[l][1] - mx);
        float e2 = expf(sc[l][2] - mx), e3 = expf(sc[l][3] - mx);
        float inv = 1.0f / (e0 + e1 + e2 + e3);
        float o = (e0 * v[0] + e1 * v[1] + e2 * v[2] + e3 * v[3]) * inv;
        g_h[l][(size_t)n * D + h * 32 + lane] = o;
    }
}

// ---------------- final outputs (float4; coef computed inline per block) ----------------
__global__ void k_final(float* __restrict__ out, int Nn) {
    __shared__ float sco[4];
    if (threadIdx.x == 0) {
        double sv[4] = { g_scores[0] / Nn, g_scores[1] / Nn, g_scores[3] / Nn, g_scores[2] / Nn };
        double mx = sv[0];
        for (int i = 1; i < 4; i++) mx = sv[i] > mx ? sv[i] : mx;
        double e[4], ss = 0.0;
        for (int i = 0; i < 4; i++) { e[i] = exp(sv[i] - mx); ss += e[i]; }
        double w[4];
        for (int i = 0; i < 4; i++) w[i] = e[i] / ss;
        sco[0] = (float)w[0];
        sco[1] = (float)w[1];
        sco[2] = (float)w[3];
        sco[3] = (float)w[2];
    }
    __syncthreads();
    size_t i4 = (size_t)blockIdx.x * blockDim.x + threadIdx.x;
    size_t ND4 = (size_t)Nn * 32;
    if (i4 >= ND4) return;
    int c4 = (int)(i4 & 31) * 4;
    float4 e0 = ((const float4*)g_emb[0])[i4];
    float4 e1 = ((const float4*)g_emb[1])[i4];
    float4 e2 = ((const float4*)g_emb[2])[i4];
    float4 e3 = ((const float4*)g_emb[3])[i4];
    float w0 = sco[0], w1 = sco[1], w2 = sco[2], w3 = sco[3];
    float4 r4;
    r4.x = w0 * e0.x + w1 * e1.x + w2 * e2.x + w3 * e3.x;
    r4.y = w0 * e0.y + w1 * e1.y + w2 * e2.y + w3 * e3.y;
    r4.z = w0 * e0.z + w1 * e1.z + w2 * e2.z + w3 * e3.z;
    r4.w = w0 * e0.w + w1 * e1.w + w2 * e2.w + w3 * e3.w;
    float4* o4 = (float4*)out;
    o4[i4] = r4;
    float4 c;
    c = *(const float4*)(g_rels[3] + c4);
    o4[ND4 + i4]     = make_float4(r4.x * c.x, r4.y * c.y, r4.z * c.z, r4.w * c.w);
    c = *(const float4*)(g_rels[0] + c4);
    o4[2 * ND4 + i4] = make_float4(r4.x * c.x, r4.y * c.y, r4.z * c.z, r4.w * c.w);
    c = *(const float4*)(g_rels[1] + c4);
    o4[3 * ND4 + i4] = make_float4(r4.x * c.x, r4.y * c.y, r4.z * c.z, r4.w * c.w);
    c = *(const float4*)(g_rels[2] + c4);
    o4[4 * ND4 + i4] = make_float4(r4.x * c.x, r4.y * c.y, r4.z * c.z, r4.w * c.w);
}

// ---------------- host orchestration ----------------
extern "C" void kernel_launch(void* const* d_in, const int* in_sizes, int n_in,
                              void* d_out, int out_size) {
    const float* features   = (const float*)d_in[0];
    const float* rel_emb    = (const float*)d_in[1];
    const int*   edge_index = (const int*)  d_in[2];
    const float* W_gcn      = (const float*)d_in[3];
    const float* b_gcn      = (const float*)d_in[4];
    const float* bn_gamma   = (const float*)d_in[5];
    const float* bn_beta    = (const float*)d_in[6];
    const float* W_rt       = (const float*)d_in[7];
    const float* b_rt       = (const float*)d_in[8];
    const float* attn_w_in  = (const float*)d_in[9];
    const float* attn_b_in  = (const float*)d_in[10];
    const float* attn_w_out = (const float*)d_in[11];
    const float* attn_b_out = (const float*)d_in[12];
    const float* alphas     = (const float*)d_in[13];
    const float* fusion_q   = (const float*)d_in[14];
    const float* fusion_w   = (const float*)d_in[15];
    const float* fusion_b   = (const float*)d_in[16];

    int Nn = in_sizes[0] / D;
    int E  = in_sizes[2] / 8;
    if (Nn > MAXN || E > EMAX) return;

    static float *emb = nullptr, *h, *agg, *qkv, *rels;
    static double *scores;
    static bool attr_done = false;
    static cudaStream_t s1 = nullptr;
    static cudaEvent_t evFork, evCSR, evG[3], evR[3];
    if (!emb) {
        cudaGetSymbolAddress((void**)&emb,    g_emb);
        cudaGetSymbolAddress((void**)&h,      g_h);
        cudaGetSymbolAddress((void**)&agg,    g_agg);
        cudaGetSymbolAddress((void**)&qkv,    g_qkv);
        cudaGetSymbolAddress((void**)&rels,   g_rels);
        cudaGetSymbolAddress((void**)&scores, g_scores);
    }
    if (!s1) {
        cudaStreamCreateWithFlags(&s1, cudaStreamNonBlocking);
        cudaEventCreateWithFlags(&evFork, cudaEventDisableTiming);
        cudaEventCreateWithFlags(&evCSR,  cudaEventDisableTiming);
        for (int i = 0; i < 3; i++) {
            cudaEventCreateWithFlags(&evG[i], cudaEventDisableTiming);
            cudaEventCreateWithFlags(&evR[i], cudaEventDisableTiming);
        }
    }
    const int SMEM_T  = 73728;
    const int SMEM_NT = 71680;
    if (!attr_done) {
        cudaFuncSetAttribute((const void*)k_gemm_tf32<false, true,  false, 0>,
                             cudaFuncAttributeMaxDynamicSharedMemorySize, SMEM_NT);
        cudaFuncSetAttribute((const void*)k_gemm_tf32<true,  false, true,  0>,
                             cudaFuncAttributeMaxDynamicSharedMemorySize, SMEM_T);
        cudaFuncSetAttribute((const void*)k_gemm_tf32<true,  false, true,  1>,
                             cudaFuncAttributeMaxDynamicSharedMemorySize, SMEM_T);
        cudaFuncSetAttribute((const void*)k_gemm_tf32<true,  false, true,  2>,
                             cudaFuncAttributeMaxDynamicSharedMemorySize, SMEM_T);
        attr_done = true;
    }

    const long S = (long)MAXN * D;
    const long Q = (long)MAXN * 384;
    const long4 ident = make_long4(0, S, 2 * S, 3 * S);
    const long4 smapo = make_long4(3 * S, 0, 2 * S, 1 * S);
    const long4 qoff  = make_long4(0, Q, 2 * Q, 3 * Q);
    const long4 zero4 = make_long4(0, 0, 0, 0);

    size_t ND = (size_t)Nn * D;
    int gElem = (int)((ND + TPB - 1) / TPB);
    int g4    = (int)(((size_t)Nn * 32 + TPB - 1) / TPB);
    int gEdge = (E + TPB - 1) / TPB;
    int gy    = (Nn + 127) / 128;
    int nb    = (Nn + 1023) / 1024;
    int gTail = (int)(((size_t)(MAXN - Nn) * D + TPB - 1) / TPB);
    cudaStream_t s0 = 0;

    // ---- fork: CSR build on s1, init + layer-0 GEMM on s0 ----
    cudaEventRecord(evFork, s0);
    cudaStreamWaitEvent(s1, evFork, 0);
    k_zero_cnt<<<(4 * MAXN + TPB - 1) / TPB, TPB, 0, s1>>>();
    k_hist<<<dim3(gEdge, 4), TPB, 0, s1>>>(edge_index, E);
    k_scan1<<<dim3(nb, 4), 1024, 0, s1>>>(Nn);
    k_scan2<<<4, 64, 0, s1>>>(nb);
    k_scan3<<<dim3(nb, 4), 1024, 0, s1>>>(Nn);
    k_fill<<<dim3(gEdge, 4), TPB, 0, s1>>>(edge_index, E);
    cudaEventRecord(evCSR, s1);

    k_init<<<gElem, TPB>>>(features, rel_emb, Nn);
    if (gTail > 0) k_zero_tail<<<gTail, TPB>>>(Nn);

    for (int i = 0; i < 3; i++) {
        const float* Wg = W_gcn + (size_t)i * D * D;
        const float* bg = b_gcn + (size_t)i * D;
        // h[r] = (emb_src * rels[r]) @ Wg ; layer 0 reads emb[0] (features) for all r
        k_gemm_tf32<false, true, false, 0><<<dim3(1, gy, 4), 256, SMEM_NT>>>(
            emb, (i == 0) ? zero4 : ident, Wg, h, ident, Nn, D, D,
            rels, nullptr, nullptr, zero4, nullptr, nullptr);
        // rels update on s1 (after this layer's GEMM consumed rels); overlaps agg/BN
        cudaEventRecord(evG[i], s0);
        cudaStreamWaitEvent(s1, evG[i], 0);
        k_rels_update<<<1, 512, 0, s1>>>(W_rt + (size_t)i * D * D, b_rt + (size_t)i * D);
        cudaEventRecord(evR[i], s1);

        if (i == 0) cudaStreamWaitEvent(s0, evCSR, 0);   // CSR ready before first agg
        if (i < 2) {
            k_agg<true><<<dim3(624, 4), TPB>>>(bg, Nn);
            k_bn_final<<<1, 512>>>(bn_gamma + (size_t)i * D, bn_beta + (size_t)i * D, Nn);
            k_bn_apply<<<dim3(g4, 4), TPB>>>((i == 0) ? features : nullptr, Nn);
            cudaStreamWaitEvent(s0, evR[i], 0);          // next GEMM needs updated rels
        } else {
            k_agg<false><<<dim3(624, 4), TPB>>>(bg, Nn);
            cudaStreamWaitEvent(s0, evR[i], 0);          // k_final needs final rels
        }
    }

    // QKV over stk[l] = agg[SMAP[l]]
    k_gemm_tf32<true, false, true, 0><<<dim3(3, gy, 4), 256, SMEM_T>>>(
        agg, smapo, attn_w_in, qkv, qoff, Nn, 384, D,
        nullptr, attn_b_in, nullptr, zero4, nullptr, nullptr);
    k_attn<<<(int)(((size_t)Nn * 128 + TPB - 1) / TPB), TPB>>>(Nn);
    // out-proj + fused blend -> emb[l]
    k_gemm_tf32<true, false, true, 1><<<dim3(1, gy, 4), 256, SMEM_T>>>(
        h, ident, attn_w_out, emb, ident, Nn, D, D,
        nullptr, attn_b_out, agg, smapo, alphas, nullptr);
    // fused score GEMMs
    k_gemm_tf32<true, false, true, 2><<<dim3(1, gy, 4), 256, SMEM_T>>>(
        emb, ident, fusion_w, h, ident, Nn, D, D,
        nullptr, fusion_b, fusion_q, zero4, nullptr, scores);
    k_final<<<g4, TPB>>>((float*)d_out, Nn);
}